// round 1
// baseline (speedup 1.0000x reference)
#include <cuda_runtime.h>
#include <math.h>

// Problem constants
#define SEQ    2048
#define BATCH  2
#define WIDTH  1024
#define NH     16
#define HD     64
#define WIN    256
#define TOK    (BATCH*SEQ)     // 4096
#define NQKV   1152            // 1024 q + 64 k + 64 v

// Scratch (device globals; no allocation allowed)
__device__ float g_Wall[NQKV * WIDTH];   // packed [Wq; Wk; Wv], row-major [1152][1024]
__device__ float g_qkv [TOK * NQKV];     // per-token q(1024) | k(64) | v(64)
__device__ float g_attn[TOK * WIDTH];    // attention output, [token][1024]

// ---------------------------------------------------------------------------
// Pack Wq/Wk/Wv into one [1152][1024] weight matrix
// ---------------------------------------------------------------------------
__global__ void pack_w(const float* __restrict__ Wq,
                       const float* __restrict__ Wk,
                       const float* __restrict__ Wv) {
    int row = blockIdx.x;
    const float* src;
    if (row < 1024)      src = Wq + (size_t)row * WIDTH;
    else if (row < 1088) src = Wk + (size_t)(row - 1024) * WIDTH;
    else                 src = Wv + (size_t)(row - 1088) * WIDTH;
    const float4* s4 = (const float4*)src;
    float4* d4 = (float4*)(g_Wall + (size_t)row * WIDTH);
    d4[threadIdx.x] = s4[threadIdx.x];   // 256 threads * 4 floats = 1024
}

// ---------------------------------------------------------------------------
// SGEMM: C[M,N] = A[M,K] @ B[N,K]^T (+ bias[N]), all row-major, fp32
// 128x128 tile, BK=8, 256 threads, 8x8 microtile with split fragments.
// M,N multiples of 128; K multiple of 8.
// ---------------------------------------------------------------------------
__global__ __launch_bounds__(256, 2)
void sgemm128(const float* __restrict__ A, const float* __restrict__ B,
              float* __restrict__ C, int M, int N, int K,
              const float* __restrict__ bias) {
    __shared__ float As[8][132];   // [k][m], padded to kill STS conflicts
    __shared__ float Bs[8][132];   // [k][n]

    int tid = threadIdx.x;
    int tx = tid & 15;
    int ty = tid >> 4;
    int m0 = blockIdx.y * 128;
    int n0 = blockIdx.x * 128;

    int lrow = tid >> 1;           // 0..127
    int lk4  = (tid & 1) * 4;      // 0 or 4

    const float* Aptr = A + (size_t)(m0 + lrow) * K + lk4;
    const float* Bptr = B + (size_t)(n0 + lrow) * K + lk4;

    float acc[8][8];
#pragma unroll
    for (int i = 0; i < 8; i++)
#pragma unroll
        for (int j = 0; j < 8; j++) acc[i][j] = 0.f;

    for (int k0 = 0; k0 < K; k0 += 8) {
        float4 av = *(const float4*)(Aptr + k0);
        float4 bv = *(const float4*)(Bptr + k0);
        __syncthreads();
        As[lk4 + 0][lrow] = av.x;
        As[lk4 + 1][lrow] = av.y;
        As[lk4 + 2][lrow] = av.z;
        As[lk4 + 3][lrow] = av.w;
        Bs[lk4 + 0][lrow] = bv.x;
        Bs[lk4 + 1][lrow] = bv.y;
        Bs[lk4 + 2][lrow] = bv.z;
        Bs[lk4 + 3][lrow] = bv.w;
        __syncthreads();
#pragma unroll
        for (int kk = 0; kk < 8; kk++) {
            float4 a0 = *(const float4*)&As[kk][ty * 4];
            float4 a1 = *(const float4*)&As[kk][64 + ty * 4];
            float4 b0 = *(const float4*)&Bs[kk][tx * 4];
            float4 b1 = *(const float4*)&Bs[kk][64 + tx * 4];
            float ar[8] = {a0.x, a0.y, a0.z, a0.w, a1.x, a1.y, a1.z, a1.w};
            float br[8] = {b0.x, b0.y, b0.z, b0.w, b1.x, b1.y, b1.z, b1.w};
#pragma unroll
            for (int i = 0; i < 8; i++)
#pragma unroll
                for (int j = 0; j < 8; j++)
                    acc[i][j] = fmaf(ar[i], br[j], acc[i][j]);
        }
    }

#pragma unroll
    for (int i = 0; i < 8; i++) {
        int rl = (i < 4) ? (ty * 4 + i) : (64 + ty * 4 + (i - 4));
        size_t rbase = (size_t)(m0 + rl) * N;
#pragma unroll
        for (int jh = 0; jh < 2; jh++) {
            int cl = (jh ? 64 + tx * 4 : tx * 4);
            int c = n0 + cl;
            float4 v = make_float4(acc[i][jh * 4 + 0], acc[i][jh * 4 + 1],
                                   acc[i][jh * 4 + 2], acc[i][jh * 4 + 3]);
            if (bias) {
                v.x += bias[c + 0]; v.y += bias[c + 1];
                v.z += bias[c + 2]; v.w += bias[c + 3];
            }
            *(float4*)&C[rbase + c] = v;
        }
    }
}

// ---------------------------------------------------------------------------
// Windowed MQA attention. One CTA per (query-tile of 64, head, batch).
// Flash-style online softmax over up to 9 key tiles of 64.
// smem: Qs_t/Ks_t transposed [dim][row] with XOR swizzle (conflict-free
// vectorized fragment loads), Vs [s][d] pad-68, Ps [r][s] pad-65.
// Thread map: 16x16, each thread owns 4 query rows x 4 cols.
// ---------------------------------------------------------------------------
#define VSTRIDE 68
#define PSTRIDE 65
#define ATTN_SMEM_FLOATS (64*64 + 64*64 + 64*VSTRIDE + 64*PSTRIDE)
#define ATTN_SMEM_BYTES  (ATTN_SMEM_FLOATS * 4)

__global__ __launch_bounds__(256, 3)
void attn_kernel() {
    extern __shared__ float sm[];
    float* Qs = sm;                    // [k][r] swizzled, 64*64
    float* Ks = Qs + 64 * 64;          // [k][c] swizzled, 64*64
    float* Vs = Ks + 64 * 64;          // [s][d], stride 68
    float* Ps = Vs + 64 * VSTRIDE;     // [r][s], stride 65

    int qt  = blockIdx.x;              // 0..31
    int h   = blockIdx.y;              // 0..15
    int b   = blockIdx.z;              // 0..1
    int tid = threadIdx.x;
    int tx  = tid & 15;
    int ty  = tid >> 4;

    // ---- load Q tile (transposed + swizzled) ----
    {
        int r  = tid >> 2;             // token row within tile, 0..63
        int qq = (tid & 3) * 16;       // dim quarter base
        const float* src = g_qkv + (size_t)(b * SEQ + qt * 64 + r) * NQKV + h * HD + qq;
#pragma unroll
        for (int j = 0; j < 4; j++) {
            float4 v = *(const float4*)(src + j * 4);
            int k = qq + j * 4;
            int g = ((k >> 4) & 3) * 8;
            int rs = r ^ g;
            Qs[(k + 0) * 64 + rs] = v.x;
            Qs[(k + 1) * 64 + rs] = v.y;
            Qs[(k + 2) * 64 + rs] = v.z;
            Qs[(k + 3) * 64 + rs] = v.w;
        }
    }

    float m_i[4], l_i[4], acc[4][4];
#pragma unroll
    for (int i = 0; i < 4; i++) {
        m_i[i] = -1e30f;
        l_i[i] = 0.f;
#pragma unroll
        for (int j = 0; j < 4; j++) acc[i][j] = 0.f;
    }
    const float scale = 0.125f;  // 1/sqrt(64)

    int ktlo = qt - 4; if (ktlo < 0) ktlo = 0;
    int kthi = qt + 4; if (kthi > SEQ / 64 - 1) kthi = SEQ / 64 - 1;

    for (int kt = ktlo; kt <= kthi; kt++) {
        __syncthreads();               // previous tile fully consumed
        // ---- load K (transposed+swizzled) and V tiles ----
        {
            int c  = tid >> 2;
            int qq = (tid & 3) * 16;
            const float* base = g_qkv + (size_t)(b * SEQ + kt * 64 + c) * NQKV;
            const float* ksrc = base + 1024 + qq;
            const float* vsrc = base + 1088 + qq;
#pragma unroll
            for (int j = 0; j < 4; j++) {
                float4 kv = *(const float4*)(ksrc + j * 4);
                int k = qq + j * 4;
                int g = ((k >> 4) & 3) * 8;
                int cs = c ^ g;
                Ks[(k + 0) * 64 + cs] = kv.x;
                Ks[(k + 1) * 64 + cs] = kv.y;
                Ks[(k + 2) * 64 + cs] = kv.z;
                Ks[(k + 3) * 64 + cs] = kv.w;
                float4 vv = *(const float4*)(vsrc + j * 4);
                *(float4*)&Vs[c * VSTRIDE + qq + j * 4] = vv;
            }
        }
        __syncthreads();

        // ---- S = Q @ K^T (64x64, each thread 4x4) ----
        float s[4][4];
#pragma unroll
        for (int i = 0; i < 4; i++)
#pragma unroll
            for (int j = 0; j < 4; j++) s[i][j] = 0.f;

#pragma unroll
        for (int kb = 0; kb < 4; kb++) {
            int g = kb * 8;
            const float* qp = &Qs[(kb * 16) * 64 + ((ty * 4) ^ g)];
            const float* kp = &Ks[(kb * 16) * 64 + ((tx * 4) ^ g)];
#pragma unroll
            for (int kk = 0; kk < 16; kk++) {
                float4 qf = *(const float4*)(qp + kk * 64);
                float4 kf = *(const float4*)(kp + kk * 64);
                float qa[4] = {qf.x, qf.y, qf.z, qf.w};
                float ka[4] = {kf.x, kf.y, kf.z, kf.w};
#pragma unroll
                for (int i = 0; i < 4; i++)
#pragma unroll
                    for (int j = 0; j < 4; j++)
                        s[i][j] = fmaf(qa[i], ka[j], s[i][j]);
            }
        }

        // ---- scale + window mask ----
        int qbase = qt * 64 + ty * 4;
        int sbase = kt * 64 + tx * 4;
#pragma unroll
        for (int i = 0; i < 4; i++)
#pragma unroll
            for (int j = 0; j < 4; j++) {
                float v = s[i][j] * scale;
                int d = (qbase + i) - (sbase + j);
                if (d > WIN || d < -WIN) v = -1e30f;
                s[i][j] = v;
            }

        // ---- online softmax update (reduce across the 16 tx lanes) ----
#pragma unroll
        for (int i = 0; i < 4; i++) {
            float mx = fmaxf(fmaxf(s[i][0], s[i][1]), fmaxf(s[i][2], s[i][3]));
#pragma unroll
            for (int off = 8; off >= 1; off >>= 1)
                mx = fmaxf(mx, __shfl_xor_sync(0xffffffffu, mx, off));
            float newm = fmaxf(m_i[i], mx);
            float corr = __expf(m_i[i] - newm);
            m_i[i] = newm;
            float rsum = 0.f;
#pragma unroll
            for (int j = 0; j < 4; j++) {
                float p = __expf(s[i][j] - newm);
                s[i][j] = p;
                rsum += p;
            }
#pragma unroll
            for (int off = 8; off >= 1; off >>= 1)
                rsum += __shfl_xor_sync(0xffffffffu, rsum, off);
            l_i[i] = l_i[i] * corr + rsum;
#pragma unroll
            for (int j = 0; j < 4; j++) acc[i][j] *= corr;
            // store P row chunk
#pragma unroll
            for (int j = 0; j < 4; j++)
                Ps[(ty * 4 + i) * PSTRIDE + tx * 4 + j] = s[i][j];
        }
        __syncthreads();

        // ---- acc += P @ V ----
#pragma unroll 8
        for (int ss = 0; ss < 64; ss++) {
            float4 vf = *(const float4*)&Vs[ss * VSTRIDE + tx * 4];
            float p0 = Ps[(ty * 4 + 0) * PSTRIDE + ss];
            float p1 = Ps[(ty * 4 + 1) * PSTRIDE + ss];
            float p2 = Ps[(ty * 4 + 2) * PSTRIDE + ss];
            float p3 = Ps[(ty * 4 + 3) * PSTRIDE + ss];
            acc[0][0] = fmaf(p0, vf.x, acc[0][0]);
            acc[0][1] = fmaf(p0, vf.y, acc[0][1]);
            acc[0][2] = fmaf(p0, vf.z, acc[0][2]);
            acc[0][3] = fmaf(p0, vf.w, acc[0][3]);
            acc[1][0] = fmaf(p1, vf.x, acc[1][0]);
            acc[1][1] = fmaf(p1, vf.y, acc[1][1]);
            acc[1][2] = fmaf(p1, vf.z, acc[1][2]);
            acc[1][3] = fmaf(p1, vf.w, acc[1][3]);
            acc[2][0] = fmaf(p2, vf.x, acc[2][0]);
            acc[2][1] = fmaf(p2, vf.y, acc[2][1]);
            acc[2][2] = fmaf(p2, vf.z, acc[2][2]);
            acc[2][3] = fmaf(p2, vf.w, acc[2][3]);
            acc[3][0] = fmaf(p3, vf.x, acc[3][0]);
            acc[3][1] = fmaf(p3, vf.y, acc[3][1]);
            acc[3][2] = fmaf(p3, vf.z, acc[3][2]);
            acc[3][3] = fmaf(p3, vf.w, acc[3][3]);
        }
    }

    // ---- finalize: divide by l, write to g_attn [token][h*64 + d] ----
#pragma unroll
    for (int i = 0; i < 4; i++) {
        float inv = 1.0f / l_i[i];
        int q = qt * 64 + ty * 4 + i;
        float4 o = make_float4(acc[i][0] * inv, acc[i][1] * inv,
                               acc[i][2] * inv, acc[i][3] * inv);
        *(float4*)&g_attn[(size_t)(b * SEQ + q) * WIDTH + h * HD + tx * 4] = o;
    }
}

// ---------------------------------------------------------------------------
// Launch
// ---------------------------------------------------------------------------
extern "C" void kernel_launch(void* const* d_in, const int* in_sizes, int n_in,
                              void* d_out, int out_size) {
    const float* x  = (const float*)d_in[0];
    const float* Wq = (const float*)d_in[1];
    const float* Wk = (const float*)d_in[2];
    const float* Wv = (const float*)d_in[3];
    const float* Wf = (const float*)d_in[4];
    const float* bf = (const float*)d_in[5];
    float* out = (float*)d_out;

    (void)in_sizes; (void)n_in; (void)out_size;

    float *pW, *pQKV, *pATT;
    cudaGetSymbolAddress((void**)&pW,   g_Wall);
    cudaGetSymbolAddress((void**)&pQKV, g_qkv);
    cudaGetSymbolAddress((void**)&pATT, g_attn);

    cudaFuncSetAttribute(attn_kernel,
                         cudaFuncAttributeMaxDynamicSharedMemorySize,
                         ATTN_SMEM_BYTES);

    // 1) pack weights
    pack_w<<<NQKV, 256>>>(Wq, Wk, Wv);

    // 2) QKV projection: [4096,1024] @ [1152,1024]^T -> [4096,1152]
    sgemm128<<<dim3(NQKV / 128, TOK / 128), 256>>>(x, pW, pQKV,
                                                   TOK, NQKV, WIDTH, nullptr);

    // 3) windowed attention
    attn_kernel<<<dim3(SEQ / 64, NH, BATCH), 256, ATTN_SMEM_BYTES>>>();

    // 4) output projection + bias: [4096,1024] @ [1024,1024]^T -> out
    sgemm128<<<dim3(WIDTH / 128, TOK / 128), 256>>>(pATT, Wf, out,
                                                    TOK, WIDTH, WIDTH, bf);
}

// round 3
// speedup vs baseline: 1.4075x; 1.4075x over previous
#include <cuda_runtime.h>
#include <cuda_bf16.h>
#include <cstdint>
#include <math.h>

// Problem constants
#define SEQ    2048
#define BATCH  2
#define WIDTH  1024
#define NH     16
#define HD     64
#define WIN    256
#define TOK    (BATCH*SEQ)     // 4096
#define NQKV   1152            // 1024 q + 64 k + 64 v

// ---------------------------------------------------------------------------
// Scratch (device globals; no allocation allowed)
// ---------------------------------------------------------------------------
__device__ float         g_qkv [TOK * NQKV];     // q(1024)|k(64)|v(64) per token
__device__ float         g_attn[TOK * WIDTH];    // attention output fp32
__device__ __nv_bfloat16 g_Ah[TOK * WIDTH],  g_Al[TOK * WIDTH];    // x hi/lo
__device__ __nv_bfloat16 g_Wh[NQKV * WIDTH], g_Wl[NQKV * WIDTH];   // [Wq;Wk;Wv] hi/lo
__device__ __nv_bfloat16 g_Fh[WIDTH * WIDTH], g_Fl[WIDTH * WIDTH]; // Wf hi/lo
__device__ __nv_bfloat16 g_Oh[TOK * WIDTH],  g_Ol[TOK * WIDTH];    // attn out hi/lo

// ---------------------------------------------------------------------------
// Helpers
// ---------------------------------------------------------------------------
__device__ __forceinline__ uint32_t smem_u32(const void* p) {
    uint32_t a;
    asm("{ .reg .u64 t; cvta.to.shared.u64 t, %1; cvt.u32.u64 %0, t; }"
        : "=r"(a) : "l"(p));
    return a;
}

#define CP_ASYNC16(sa, ga) \
    asm volatile("cp.async.cg.shared.global [%0], [%1], 16;" :: "r"(sa), "l"(ga))
#define CP_COMMIT() asm volatile("cp.async.commit_group;" ::: "memory")
#define CP_WAIT1()  asm volatile("cp.async.wait_group 1;" ::: "memory")
#define CP_WAIT0()  asm volatile("cp.async.wait_group 0;" ::: "memory")

#define LDSM_X4(r0, r1, r2, r3, addr) \
    asm volatile("ldmatrix.sync.aligned.m8n8.x4.shared.b16 {%0,%1,%2,%3}, [%4];" \
        : "=r"(r0), "=r"(r1), "=r"(r2), "=r"(r3) : "r"(addr))

__device__ __forceinline__ void mma16816(float* c, const uint32_t* a,
                                         uint32_t b0, uint32_t b1) {
    asm volatile(
        "mma.sync.aligned.m16n8k16.row.col.f32.bf16.bf16.f32 "
        "{%0,%1,%2,%3}, {%4,%5,%6,%7}, {%8,%9}, {%0,%1,%2,%3};"
        : "+f"(c[0]), "+f"(c[1]), "+f"(c[2]), "+f"(c[3])
        : "r"(a[0]), "r"(a[1]), "r"(a[2]), "r"(a[3]), "r"(b0), "r"(b1));
}

// ---------------------------------------------------------------------------
// fp32 -> bf16 hi/lo split conversion
// ---------------------------------------------------------------------------
__device__ __forceinline__ void split_bf16(float v, __nv_bfloat16& h, __nv_bfloat16& l) {
    h = __float2bfloat16(v);
    l = __float2bfloat16(v - __bfloat162float(h));
}

__global__ void convert_hl(const float* __restrict__ src,
                           __nv_bfloat16* __restrict__ hi,
                           __nv_bfloat16* __restrict__ lo, int n) {
    int i = (blockIdx.x * blockDim.x + threadIdx.x) * 4;
    if (i >= n) return;
    float4 v = *(const float4*)(src + i);
    __nv_bfloat16 h0, h1, h2, h3, l0, l1, l2, l3;
    split_bf16(v.x, h0, l0); split_bf16(v.y, h1, l1);
    split_bf16(v.z, h2, l2); split_bf16(v.w, h3, l3);
    __nv_bfloat162* H = (__nv_bfloat162*)(hi + i);
    __nv_bfloat162* L = (__nv_bfloat162*)(lo + i);
    H[0] = __nv_bfloat162(h0, h1); H[1] = __nv_bfloat162(h2, h3);
    L[0] = __nv_bfloat162(l0, l1); L[1] = __nv_bfloat162(l2, l3);
}

// pack Wq/Wk/Wv rows -> [1152][1024] bf16 hi/lo
__global__ void convert_w(const float* __restrict__ Wq, const float* __restrict__ Wk,
                          const float* __restrict__ Wv) {
    int row = blockIdx.x;
    const float* src;
    if (row < 1024)      src = Wq + (size_t)row * WIDTH;
    else if (row < 1088) src = Wk + (size_t)(row - 1024) * WIDTH;
    else                 src = Wv + (size_t)(row - 1088) * WIDTH;
    int c = threadIdx.x * 4;
    float4 v = *(const float4*)(src + c);
    __nv_bfloat16 h0, h1, h2, h3, l0, l1, l2, l3;
    split_bf16(v.x, h0, l0); split_bf16(v.y, h1, l1);
    split_bf16(v.z, h2, l2); split_bf16(v.w, h3, l3);
    size_t base = (size_t)row * WIDTH + c;
    __nv_bfloat162* H = (__nv_bfloat162*)(g_Wh + base);
    __nv_bfloat162* L = (__nv_bfloat162*)(g_Wl + base);
    H[0] = __nv_bfloat162(h0, h1); H[1] = __nv_bfloat162(h2, h3);
    L[0] = __nv_bfloat162(l0, l1); L[1] = __nv_bfloat162(l2, l3);
}

// ---------------------------------------------------------------------------
// mma.sync GEMM: C[M,N] = A[M,K] @ B[N,K]^T (+bias), fp32-accurate via
// bf16 hi/lo split: AhBh + AhBl + AlBh, fp32 accumulate in registers.
// Tile 128x128x32, 8 warps (warp tile 64x32), double-buffered cp.async.
// smem row stride 80B (5 x 16B chunks) -> conflict-free ldmatrix.
// ---------------------------------------------------------------------------
#define BK 32
#define ROWB 80                       // bytes per smem row (32 bf16 data + pad)
#define ARR_B (128 * ROWB)            // 10240 B per sub-array
#define STAGE_B (4 * ARR_B)           // Ah | Al | Bh | Bl
#define GEMM_SMEM (2 * STAGE_B)       // 81920 B

__global__ __launch_bounds__(256, 1)
void mmagemm(const __nv_bfloat16* __restrict__ Ah, const __nv_bfloat16* __restrict__ Al,
             const __nv_bfloat16* __restrict__ Bh, const __nv_bfloat16* __restrict__ Bl,
             float* __restrict__ C, int M, int N, int K,
             const float* __restrict__ bias) {
    extern __shared__ char smem[];
    uint32_t sb = smem_u32(smem);
    const int tid  = threadIdx.x;
    const int lane = tid & 31;
    const int wid  = tid >> 5;
    const int wm   = wid >> 2;        // 0..1  (M direction, 64 rows each)
    const int wn   = wid & 3;         // 0..3  (N direction, 32 cols each)
    const int m0 = blockIdx.y * 128;
    const int n0 = blockIdx.x * 128;
    const int NK = K / BK;
    const size_t RS = (size_t)K * 2;  // row stride in bytes (A and B)

    // cp.async mapping: thread t loads 32B (2 chunks) per sub-array:
    // row = t/2, chunk col = (t&1)*2 + {0,1}
    const int crow = tid >> 1;
    const int ccol = (tid & 1) * 2;
    const uint32_t s_off0 = crow * ROWB + ccol * 16;
    const char* gA0 = (const char*)Ah + (size_t)(m0 + crow) * RS + ccol * 16;
    const char* gA1 = (const char*)Al + (size_t)(m0 + crow) * RS + ccol * 16;
    const char* gB0 = (const char*)Bh + (size_t)(n0 + crow) * RS + ccol * 16;
    const char* gB1 = (const char*)Bl + (size_t)(n0 + crow) * RS + ccol * 16;

    auto load_stage = [&](int s, int it) {
        uint32_t st = sb + s * STAGE_B;
        size_t kb = (size_t)it * (BK * 2);
        CP_ASYNC16(st + 0 * ARR_B + s_off0,      gA0 + kb);
        CP_ASYNC16(st + 0 * ARR_B + s_off0 + 16, gA0 + kb + 16);
        CP_ASYNC16(st + 1 * ARR_B + s_off0,      gA1 + kb);
        CP_ASYNC16(st + 1 * ARR_B + s_off0 + 16, gA1 + kb + 16);
        CP_ASYNC16(st + 2 * ARR_B + s_off0,      gB0 + kb);
        CP_ASYNC16(st + 2 * ARR_B + s_off0 + 16, gB0 + kb + 16);
        CP_ASYNC16(st + 3 * ARR_B + s_off0,      gB1 + kb);
        CP_ASYNC16(st + 3 * ARR_B + s_off0 + 16, gB1 + kb + 16);
    };

    float acc[4][4][4];
#pragma unroll
    for (int i = 0; i < 4; i++)
#pragma unroll
        for (int j = 0; j < 4; j++)
#pragma unroll
            for (int q = 0; q < 4; q++) acc[i][j][q] = 0.f;

    // ldmatrix lane-address components (row/chunk within tile, x ROWB/16)
    const int asub = lane >> 3;
    const int a_row_in = (lane & 7) + 8 * (asub & 1);       // within 16-row tile
    const int a_chunk  = asub >> 1;                          // 0/1 within kstep
    const int b_row_in = (lane & 7) + 8 * (asub >> 1);       // within 16-n pair
    const int b_chunk  = asub & 1;

    load_stage(0, 0);
    CP_COMMIT();

    for (int it = 0; it < NK; ++it) {
        if (it + 1 < NK) { load_stage((it + 1) & 1, it + 1); CP_COMMIT(); CP_WAIT1(); }
        else             { CP_WAIT0(); }
        __syncthreads();

        uint32_t st  = sb + (it & 1) * STAGE_B;
        uint32_t pAh = st;
        uint32_t pAl = st + ARR_B;
        uint32_t pBh = st + 2 * ARR_B;
        uint32_t pBl = st + 3 * ARR_B;

#pragma unroll
        for (int kk = 0; kk < 2; kk++) {
            uint32_t ah[4][4], al[4][4], bh[2][4], bl[2][4];
#pragma unroll
            for (int mt = 0; mt < 4; mt++) {
                uint32_t off = (uint32_t)((wm * 64 + mt * 16 + a_row_in) * ROWB +
                                          (kk * 2 + a_chunk) * 16);
                LDSM_X4(ah[mt][0], ah[mt][1], ah[mt][2], ah[mt][3], pAh + off);
                LDSM_X4(al[mt][0], al[mt][1], al[mt][2], al[mt][3], pAl + off);
            }
#pragma unroll
            for (int p = 0; p < 2; p++) {
                uint32_t off = (uint32_t)((wn * 32 + p * 16 + b_row_in) * ROWB +
                                          (kk * 2 + b_chunk) * 16);
                LDSM_X4(bh[p][0], bh[p][1], bh[p][2], bh[p][3], pBh + off);
                LDSM_X4(bl[p][0], bl[p][1], bl[p][2], bl[p][3], pBl + off);
            }
#pragma unroll
            for (int mt = 0; mt < 4; mt++)
#pragma unroll
                for (int p = 0; p < 2; p++)
#pragma unroll
                    for (int hh = 0; hh < 2; hh++) {
                        int nt = p * 2 + hh;
                        mma16816(acc[mt][nt], ah[mt], bh[p][hh * 2], bh[p][hh * 2 + 1]);
                        mma16816(acc[mt][nt], ah[mt], bl[p][hh * 2], bl[p][hh * 2 + 1]);
                        mma16816(acc[mt][nt], al[mt], bh[p][hh * 2], bh[p][hh * 2 + 1]);
                    }
        }
        __syncthreads();
    }

    // epilogue
    const int gid = lane >> 2;        // 0..7
    const int qid = lane & 3;         // 0..3
#pragma unroll
    for (int mt = 0; mt < 4; mt++) {
        int r0 = m0 + wm * 64 + mt * 16 + gid;
#pragma unroll
        for (int nt = 0; nt < 4; nt++) {
            int c = n0 + wn * 32 + nt * 8 + qid * 2;
            float b0 = 0.f, b1 = 0.f;
            if (bias) { b0 = bias[c]; b1 = bias[c + 1]; }
            float2 v0 = make_float2(acc[mt][nt][0] + b0, acc[mt][nt][1] + b1);
            float2 v1 = make_float2(acc[mt][nt][2] + b0, acc[mt][nt][3] + b1);
            *(float2*)&C[(size_t)r0 * N + c] = v0;
            *(float2*)&C[(size_t)(r0 + 8) * N + c] = v1;
        }
    }
}

// ---------------------------------------------------------------------------
// Windowed MQA attention (fp32 SIMT, unchanged)
// ---------------------------------------------------------------------------
#define VSTRIDE 68
#define PSTRIDE 65
#define ATTN_SMEM_FLOATS (64*64 + 64*64 + 64*VSTRIDE + 64*PSTRIDE)
#define ATTN_SMEM_BYTES  (ATTN_SMEM_FLOATS * 4)

__global__ __launch_bounds__(256, 3)
void attn_kernel() {
    extern __shared__ float sm[];
    float* Qs = sm;
    float* Ks = Qs + 64 * 64;
    float* Vs = Ks + 64 * 64;
    float* Ps = Vs + 64 * VSTRIDE;

    int qt  = blockIdx.x;
    int h   = blockIdx.y;
    int b   = blockIdx.z;
    int tid = threadIdx.x;
    int tx  = tid & 15;
    int ty  = tid >> 4;

    {
        int r  = tid >> 2;
        int qq = (tid & 3) * 16;
        const float* src = g_qkv + (size_t)(b * SEQ + qt * 64 + r) * NQKV + h * HD + qq;
#pragma unroll
        for (int j = 0; j < 4; j++) {
            float4 v = *(const float4*)(src + j * 4);
            int k = qq + j * 4;
            int g = ((k >> 4) & 3) * 8;
            int rs = r ^ g;
            Qs[(k + 0) * 64 + rs] = v.x;
            Qs[(k + 1) * 64 + rs] = v.y;
            Qs[(k + 2) * 64 + rs] = v.z;
            Qs[(k + 3) * 64 + rs] = v.w;
        }
    }

    float m_i[4], l_i[4], acc[4][4];
#pragma unroll
    for (int i = 0; i < 4; i++) {
        m_i[i] = -1e30f; l_i[i] = 0.f;
#pragma unroll
        for (int j = 0; j < 4; j++) acc[i][j] = 0.f;
    }
    const float scale = 0.125f;

    int ktlo = qt - 4; if (ktlo < 0) ktlo = 0;
    int kthi = qt + 4; if (kthi > SEQ / 64 - 1) kthi = SEQ / 64 - 1;

    for (int kt = ktlo; kt <= kthi; kt++) {
        __syncthreads();
        {
            int c  = tid >> 2;
            int qq = (tid & 3) * 16;
            const float* base = g_qkv + (size_t)(b * SEQ + kt * 64 + c) * NQKV;
            const float* ksrc = base + 1024 + qq;
            const float* vsrc = base + 1088 + qq;
#pragma unroll
            for (int j = 0; j < 4; j++) {
                float4 kv = *(const float4*)(ksrc + j * 4);
                int k = qq + j * 4;
                int g = ((k >> 4) & 3) * 8;
                int cs = c ^ g;
                Ks[(k + 0) * 64 + cs] = kv.x;
                Ks[(k + 1) * 64 + cs] = kv.y;
                Ks[(k + 2) * 64 + cs] = kv.z;
                Ks[(k + 3) * 64 + cs] = kv.w;
                float4 vv = *(const float4*)(vsrc + j * 4);
                *(float4*)&Vs[c * VSTRIDE + qq + j * 4] = vv;
            }
        }
        __syncthreads();

        float s[4][4];
#pragma unroll
        for (int i = 0; i < 4; i++)
#pragma unroll
            for (int j = 0; j < 4; j++) s[i][j] = 0.f;

#pragma unroll
        for (int kb = 0; kb < 4; kb++) {
            int g = kb * 8;
            const float* qp = &Qs[(kb * 16) * 64 + ((ty * 4) ^ g)];
            const float* kp = &Ks[(kb * 16) * 64 + ((tx * 4) ^ g)];
#pragma unroll
            for (int kk = 0; kk < 16; kk++) {
                float4 qf = *(const float4*)(qp + kk * 64);
                float4 kf = *(const float4*)(kp + kk * 64);
                float qa[4] = {qf.x, qf.y, qf.z, qf.w};
                float ka[4] = {kf.x, kf.y, kf.z, kf.w};
#pragma unroll
                for (int i = 0; i < 4; i++)
#pragma unroll
                    for (int j = 0; j < 4; j++)
                        s[i][j] = fmaf(qa[i], ka[j], s[i][j]);
            }
        }

        int qbase = qt * 64 + ty * 4;
        int sbase = kt * 64 + tx * 4;
#pragma unroll
        for (int i = 0; i < 4; i++)
#pragma unroll
            for (int j = 0; j < 4; j++) {
                float v = s[i][j] * scale;
                int d = (qbase + i) - (sbase + j);
                if (d > WIN || d < -WIN) v = -1e30f;
                s[i][j] = v;
            }

#pragma unroll
        for (int i = 0; i < 4; i++) {
            float mx = fmaxf(fmaxf(s[i][0], s[i][1]), fmaxf(s[i][2], s[i][3]));
#pragma unroll
            for (int off = 8; off >= 1; off >>= 1)
                mx = fmaxf(mx, __shfl_xor_sync(0xffffffffu, mx, off));
            float newm = fmaxf(m_i[i], mx);
            float corr = __expf(m_i[i] - newm);
            m_i[i] = newm;
            float rsum = 0.f;
#pragma unroll
            for (int j = 0; j < 4; j++) {
                float p = __expf(s[i][j] - newm);
                s[i][j] = p;
                rsum += p;
            }
#pragma unroll
            for (int off = 8; off >= 1; off >>= 1)
                rsum += __shfl_xor_sync(0xffffffffu, rsum, off);
            l_i[i] = l_i[i] * corr + rsum;
#pragma unroll
            for (int j = 0; j < 4; j++) acc[i][j] *= corr;
#pragma unroll
            for (int j = 0; j < 4; j++)
                Ps[(ty * 4 + i) * PSTRIDE + tx * 4 + j] = s[i][j];
        }
        __syncthreads();

#pragma unroll 8
        for (int ss = 0; ss < 64; ss++) {
            float4 vf = *(const float4*)&Vs[ss * VSTRIDE + tx * 4];
            float p0 = Ps[(ty * 4 + 0) * PSTRIDE + ss];
            float p1 = Ps[(ty * 4 + 1) * PSTRIDE + ss];
            float p2 = Ps[(ty * 4 + 2) * PSTRIDE + ss];
            float p3 = Ps[(ty * 4 + 3) * PSTRIDE + ss];
            acc[0][0] = fmaf(p0, vf.x, acc[0][0]);
            acc[0][1] = fmaf(p0, vf.y, acc[0][1]);
            acc[0][2] = fmaf(p0, vf.z, acc[0][2]);
            acc[0][3] = fmaf(p0, vf.w, acc[0][3]);
            acc[1][0] = fmaf(p1, vf.x, acc[1][0]);
            acc[1][1] = fmaf(p1, vf.y, acc[1][1]);
            acc[1][2] = fmaf(p1, vf.z, acc[1][2]);
            acc[1][3] = fmaf(p1, vf.w, acc[1][3]);
            acc[2][0] = fmaf(p2, vf.x, acc[2][0]);
            acc[2][1] = fmaf(p2, vf.y, acc[2][1]);
            acc[2][2] = fmaf(p2, vf.z, acc[2][2]);
            acc[2][3] = fmaf(p2, vf.w, acc[2][3]);
            acc[3][0] = fmaf(p3, vf.x, acc[3][0]);
            acc[3][1] = fmaf(p3, vf.y, acc[3][1]);
            acc[3][2] = fmaf(p3, vf.z, acc[3][2]);
            acc[3][3] = fmaf(p3, vf.w, acc[3][3]);
        }
    }

#pragma unroll
    for (int i = 0; i < 4; i++) {
        float inv = 1.0f / l_i[i];
        int q = qt * 64 + ty * 4 + i;
        float4 o = make_float4(acc[i][0] * inv, acc[i][1] * inv,
                               acc[i][2] * inv, acc[i][3] * inv);
        *(float4*)&g_attn[(size_t)(b * SEQ + q) * WIDTH + h * HD + tx * 4] = o;
    }
}

// ---------------------------------------------------------------------------
// Launch
// ---------------------------------------------------------------------------
extern "C" void kernel_launch(void* const* d_in, const int* in_sizes, int n_in,
                              void* d_out, int out_size) {
    const float* x  = (const float*)d_in[0];
    const float* Wq = (const float*)d_in[1];
    const float* Wk = (const float*)d_in[2];
    const float* Wv = (const float*)d_in[3];
    const float* Wf = (const float*)d_in[4];
    const float* bf = (const float*)d_in[5];
    float* out = (float*)d_out;
    (void)in_sizes; (void)n_in; (void)out_size;

    float *pQKV, *pATT;
    __nv_bfloat16 *pAh, *pAl, *pWh, *pWl, *pFh, *pFl, *pOh, *pOl;
    cudaGetSymbolAddress((void**)&pQKV, g_qkv);
    cudaGetSymbolAddress((void**)&pATT, g_attn);
    cudaGetSymbolAddress((void**)&pAh, g_Ah);
    cudaGetSymbolAddress((void**)&pAl, g_Al);
    cudaGetSymbolAddress((void**)&pWh, g_Wh);
    cudaGetSymbolAddress((void**)&pWl, g_Wl);
    cudaGetSymbolAddress((void**)&pFh, g_Fh);
    cudaGetSymbolAddress((void**)&pFl, g_Fl);
    cudaGetSymbolAddress((void**)&pOh, g_Oh);
    cudaGetSymbolAddress((void**)&pOl, g_Ol);

    cudaFuncSetAttribute(attn_kernel,
                         cudaFuncAttributeMaxDynamicSharedMemorySize, ATTN_SMEM_BYTES);
    cudaFuncSetAttribute(mmagemm,
                         cudaFuncAttributeMaxDynamicSharedMemorySize, GEMM_SMEM);

    // conversions
    convert_hl<<<TOK * WIDTH / 1024, 256>>>(x, pAh, pAl, TOK * WIDTH);
    convert_w<<<NQKV, 256>>>(Wq, Wk, Wv);
    convert_hl<<<WIDTH * WIDTH / 1024, 256>>>(Wf, pFh, pFl, WIDTH * WIDTH);

    // QKV projection: [4096,1024] @ [1152,1024]^T -> [4096,1152]
    mmagemm<<<dim3(NQKV / 128, TOK / 128), 256, GEMM_SMEM>>>(
        pAh, pAl, pWh, pWl, pQKV, TOK, NQKV, WIDTH, nullptr);

    // windowed attention
    attn_kernel<<<dim3(SEQ / 64, NH, BATCH), 256, ATTN_SMEM_BYTES>>>();

    // attn out -> bf16 hi/lo, then output projection + bias
    convert_hl<<<TOK * WIDTH / 1024, 256>>>(pATT, pOh, pOl, TOK * WIDTH);
    mmagemm<<<dim3(WIDTH / 128, TOK / 128), 256, GEMM_SMEM>>>(
        pOh, pOl, pFh, pFl, out, TOK, WIDTH, WIDTH, bf);
}

// round 4
// speedup vs baseline: 2.3424x; 1.6642x over previous
#include <cuda_runtime.h>
#include <cuda_bf16.h>
#include <cstdint>
#include <math.h>

// Problem constants
#define SEQ    2048
#define BATCH  2
#define WIDTH  1024
#define NH     16
#define HD     64
#define WIN    256
#define TOK    (BATCH*SEQ)     // 4096
#define NQKV   1152            // 1024 q + 64 k + 64 v

// ---------------------------------------------------------------------------
// Scratch (device globals; no allocation allowed)
// ---------------------------------------------------------------------------
__device__ __nv_bfloat16 g_Ah[TOK * WIDTH],  g_Al[TOK * WIDTH];    // x hi/lo
__device__ __nv_bfloat16 g_Wh[NQKV * WIDTH], g_Wl[NQKV * WIDTH];   // [Wq;Wk;Wv] hi/lo
__device__ __nv_bfloat16 g_Fh[WIDTH * WIDTH], g_Fl[WIDTH * WIDTH]; // Wf hi/lo
__device__ __nv_bfloat16 g_Qh[TOK * NQKV],  g_Ql[TOK * NQKV];      // qkv hi/lo
__device__ __nv_bfloat16 g_Oh[TOK * WIDTH], g_Ol[TOK * WIDTH];     // attn out hi/lo

// ---------------------------------------------------------------------------
// Helpers
// ---------------------------------------------------------------------------
__device__ __forceinline__ uint32_t smem_u32(const void* p) {
    uint32_t a;
    asm("{ .reg .u64 t; cvta.to.shared.u64 t, %1; cvt.u32.u64 %0, t; }"
        : "=r"(a) : "l"(p));
    return a;
}

#define CP_ASYNC16(sa, ga) \
    asm volatile("cp.async.cg.shared.global [%0], [%1], 16;" :: "r"(sa), "l"(ga))
#define CP_COMMIT() asm volatile("cp.async.commit_group;" ::: "memory")
#define CP_WAIT2()  asm volatile("cp.async.wait_group 2;" ::: "memory")
#define CP_WAIT1()  asm volatile("cp.async.wait_group 1;" ::: "memory")
#define CP_WAIT0()  asm volatile("cp.async.wait_group 0;" ::: "memory")

#define LDSM_X4(r0, r1, r2, r3, addr) \
    asm volatile("ldmatrix.sync.aligned.m8n8.x4.shared.b16 {%0,%1,%2,%3}, [%4];" \
        : "=r"(r0), "=r"(r1), "=r"(r2), "=r"(r3) : "r"(addr))
#define LDSM_X4T(r0, r1, r2, r3, addr) \
    asm volatile("ldmatrix.sync.aligned.m8n8.x4.trans.shared.b16 {%0,%1,%2,%3}, [%4];" \
        : "=r"(r0), "=r"(r1), "=r"(r2), "=r"(r3) : "r"(addr))

__device__ __forceinline__ void mma16816(float* c, const uint32_t* a,
                                         uint32_t b0, uint32_t b1) {
    asm volatile(
        "mma.sync.aligned.m16n8k16.row.col.f32.bf16.bf16.f32 "
        "{%0,%1,%2,%3}, {%4,%5,%6,%7}, {%8,%9}, {%0,%1,%2,%3};"
        : "+f"(c[0]), "+f"(c[1]), "+f"(c[2]), "+f"(c[3])
        : "r"(a[0]), "r"(a[1]), "r"(a[2]), "r"(a[3]), "r"(b0), "r"(b1));
}

__device__ __forceinline__ uint32_t packbf(__nv_bfloat16 a, __nv_bfloat16 b) {
    __nv_bfloat162 t; t.x = a; t.y = b;
    return *(uint32_t*)&t;
}
__device__ __forceinline__ void split2(float a, float b, uint32_t& hi, uint32_t& lo) {
    __nv_bfloat16 ah = __float2bfloat16(a), bh = __float2bfloat16(b);
    hi = packbf(ah, bh);
    lo = packbf(__float2bfloat16(a - __bfloat162float(ah)),
                __float2bfloat16(b - __bfloat162float(bh)));
}
__device__ __forceinline__ void split_bf16(float v, __nv_bfloat16& h, __nv_bfloat16& l) {
    h = __float2bfloat16(v);
    l = __float2bfloat16(v - __bfloat162float(h));
}

// ---------------------------------------------------------------------------
// fp32 -> bf16 hi/lo conversions
// ---------------------------------------------------------------------------
__global__ void convert_hl(const float* __restrict__ src,
                           __nv_bfloat16* __restrict__ hi,
                           __nv_bfloat16* __restrict__ lo, int n) {
    int i = (blockIdx.x * blockDim.x + threadIdx.x) * 4;
    if (i >= n) return;
    float4 v = *(const float4*)(src + i);
    __nv_bfloat16 h0, h1, h2, h3, l0, l1, l2, l3;
    split_bf16(v.x, h0, l0); split_bf16(v.y, h1, l1);
    split_bf16(v.z, h2, l2); split_bf16(v.w, h3, l3);
    __nv_bfloat162* H = (__nv_bfloat162*)(hi + i);
    __nv_bfloat162* L = (__nv_bfloat162*)(lo + i);
    H[0] = __nv_bfloat162(h0, h1); H[1] = __nv_bfloat162(h2, h3);
    L[0] = __nv_bfloat162(l0, l1); L[1] = __nv_bfloat162(l2, l3);
}

__global__ void convert_w(const float* __restrict__ Wq, const float* __restrict__ Wk,
                          const float* __restrict__ Wv) {
    int row = blockIdx.x;
    const float* src;
    if (row < 1024)      src = Wq + (size_t)row * WIDTH;
    else if (row < 1088) src = Wk + (size_t)(row - 1024) * WIDTH;
    else                 src = Wv + (size_t)(row - 1088) * WIDTH;
    int c = threadIdx.x * 4;
    float4 v = *(const float4*)(src + c);
    __nv_bfloat16 h0, h1, h2, h3, l0, l1, l2, l3;
    split_bf16(v.x, h0, l0); split_bf16(v.y, h1, l1);
    split_bf16(v.z, h2, l2); split_bf16(v.w, h3, l3);
    size_t base = (size_t)row * WIDTH + c;
    __nv_bfloat162* H = (__nv_bfloat162*)(g_Wh + base);
    __nv_bfloat162* L = (__nv_bfloat162*)(g_Wl + base);
    H[0] = __nv_bfloat162(h0, h1); H[1] = __nv_bfloat162(h2, h3);
    L[0] = __nv_bfloat162(l0, l1); L[1] = __nv_bfloat162(l2, l3);
}

// ---------------------------------------------------------------------------
// mma.sync GEMM: C = A @ B^T (+bias), bf16 hi/lo split, 128x128x32 tile,
// 8 warps, 3-stage cp.async pipeline.  Output: fp32 (C) or bf16 hi/lo (Ch/Cl).
// ---------------------------------------------------------------------------
#define BK 32
#define ROWB 80
#define ARR_B (128 * ROWB)
#define STAGE_B (4 * ARR_B)
#define GEMM_SMEM (3 * STAGE_B)       // 122880 B

__global__ __launch_bounds__(256)
void mmagemm(const __nv_bfloat16* __restrict__ Ah, const __nv_bfloat16* __restrict__ Al,
             const __nv_bfloat16* __restrict__ Bh, const __nv_bfloat16* __restrict__ Bl,
             float* __restrict__ C,
             __nv_bfloat16* __restrict__ Ch, __nv_bfloat16* __restrict__ Cl,
             int M, int N, int K, const float* __restrict__ bias) {
    extern __shared__ char smem[];
    uint32_t sb = smem_u32(smem);
    const int tid  = threadIdx.x;
    const int lane = tid & 31;
    const int wid  = tid >> 5;
    const int wm   = wid >> 2;
    const int wn   = wid & 3;
    const int m0 = blockIdx.y * 128;
    const int n0 = blockIdx.x * 128;
    const int NK = K / BK;
    const size_t RS = (size_t)K * 2;

    const int crow = tid >> 1;
    const int ccol = (tid & 1) * 2;
    const uint32_t s_off0 = crow * ROWB + ccol * 16;
    const char* gA0 = (const char*)Ah + (size_t)(m0 + crow) * RS + ccol * 16;
    const char* gA1 = (const char*)Al + (size_t)(m0 + crow) * RS + ccol * 16;
    const char* gB0 = (const char*)Bh + (size_t)(n0 + crow) * RS + ccol * 16;
    const char* gB1 = (const char*)Bl + (size_t)(n0 + crow) * RS + ccol * 16;

    auto load_stage = [&](int s, int it) {
        uint32_t st = sb + s * STAGE_B;
        size_t kb = (size_t)it * (BK * 2);
        CP_ASYNC16(st + 0 * ARR_B + s_off0,      gA0 + kb);
        CP_ASYNC16(st + 0 * ARR_B + s_off0 + 16, gA0 + kb + 16);
        CP_ASYNC16(st + 1 * ARR_B + s_off0,      gA1 + kb);
        CP_ASYNC16(st + 1 * ARR_B + s_off0 + 16, gA1 + kb + 16);
        CP_ASYNC16(st + 2 * ARR_B + s_off0,      gB0 + kb);
        CP_ASYNC16(st + 2 * ARR_B + s_off0 + 16, gB0 + kb + 16);
        CP_ASYNC16(st + 3 * ARR_B + s_off0,      gB1 + kb);
        CP_ASYNC16(st + 3 * ARR_B + s_off0 + 16, gB1 + kb + 16);
    };

    float acc[4][4][4];
#pragma unroll
    for (int i = 0; i < 4; i++)
#pragma unroll
        for (int j = 0; j < 4; j++)
#pragma unroll
            for (int q = 0; q < 4; q++) acc[i][j][q] = 0.f;

    const int asub = lane >> 3;
    const int a_row_in = (lane & 7) + 8 * (asub & 1);
    const int a_chunk  = asub >> 1;
    const int b_row_in = (lane & 7) + 8 * (asub >> 1);
    const int b_chunk  = asub & 1;

    load_stage(0, 0); CP_COMMIT();
    load_stage(1, 1); CP_COMMIT();

    for (int it = 0; it < NK; ++it) {
        if (it + 2 < NK) { load_stage((it + 2) % 3, it + 2); CP_COMMIT(); }
        if (it + 2 < NK)      CP_WAIT2();
        else if (it + 1 < NK) CP_WAIT1();
        else                  CP_WAIT0();
        __syncthreads();

        uint32_t st  = sb + (it % 3) * STAGE_B;
        uint32_t pAh = st;
        uint32_t pAl = st + ARR_B;
        uint32_t pBh = st + 2 * ARR_B;
        uint32_t pBl = st + 3 * ARR_B;

#pragma unroll
        for (int kk = 0; kk < 2; kk++) {
            uint32_t ah[4][4], al[4][4], bh[2][4], bl[2][4];
#pragma unroll
            for (int mt = 0; mt < 4; mt++) {
                uint32_t off = (uint32_t)((wm * 64 + mt * 16 + a_row_in) * ROWB +
                                          (kk * 2 + a_chunk) * 16);
                LDSM_X4(ah[mt][0], ah[mt][1], ah[mt][2], ah[mt][3], pAh + off);
                LDSM_X4(al[mt][0], al[mt][1], al[mt][2], al[mt][3], pAl + off);
            }
#pragma unroll
            for (int p = 0; p < 2; p++) {
                uint32_t off = (uint32_t)((wn * 32 + p * 16 + b_row_in) * ROWB +
                                          (kk * 2 + b_chunk) * 16);
                LDSM_X4(bh[p][0], bh[p][1], bh[p][2], bh[p][3], pBh + off);
                LDSM_X4(bl[p][0], bl[p][1], bl[p][2], bl[p][3], pBl + off);
            }
#pragma unroll
            for (int mt = 0; mt < 4; mt++)
#pragma unroll
                for (int p = 0; p < 2; p++)
#pragma unroll
                    for (int hh = 0; hh < 2; hh++) {
                        int nt = p * 2 + hh;
                        mma16816(acc[mt][nt], ah[mt], bh[p][hh * 2], bh[p][hh * 2 + 1]);
                        mma16816(acc[mt][nt], ah[mt], bl[p][hh * 2], bl[p][hh * 2 + 1]);
                        mma16816(acc[mt][nt], al[mt], bh[p][hh * 2], bh[p][hh * 2 + 1]);
                    }
        }
        __syncthreads();
    }

    const int gid = lane >> 2;
    const int qid = lane & 3;
#pragma unroll
    for (int mt = 0; mt < 4; mt++) {
        int r0 = m0 + wm * 64 + mt * 16 + gid;
#pragma unroll
        for (int nt = 0; nt < 4; nt++) {
            int c = n0 + wn * 32 + nt * 8 + qid * 2;
            if (C) {
                float b0 = 0.f, b1 = 0.f;
                if (bias) { b0 = bias[c]; b1 = bias[c + 1]; }
                *(float2*)&C[(size_t)r0 * N + c] =
                    make_float2(acc[mt][nt][0] + b0, acc[mt][nt][1] + b1);
                *(float2*)&C[(size_t)(r0 + 8) * N + c] =
                    make_float2(acc[mt][nt][2] + b0, acc[mt][nt][3] + b1);
            } else {
                uint32_t hi, lo;
                split2(acc[mt][nt][0], acc[mt][nt][1], hi, lo);
                *(uint32_t*)&Ch[(size_t)r0 * N + c] = hi;
                *(uint32_t*)&Cl[(size_t)r0 * N + c] = lo;
                split2(acc[mt][nt][2], acc[mt][nt][3], hi, lo);
                *(uint32_t*)&Ch[(size_t)(r0 + 8) * N + c] = hi;
                *(uint32_t*)&Cl[(size_t)(r0 + 8) * N + c] = lo;
            }
        }
    }
}

// ---------------------------------------------------------------------------
// Tensor-core windowed MQA flash attention.
// CTA = (qtile 64, head, batch); 4 warps x 16 q rows; K/V double-buffered.
// All GEMMs bf16 hi/lo split; online softmax in fp32 registers.
// ---------------------------------------------------------------------------
#define AROWB 144                     // 64 bf16 = 128B + 16B pad
#define ATN_ARR   (64 * AROWB)        // 9216 B per tile array
#define ATN_SQH   0
#define ATN_SQL   ATN_ARR
#define ATN_STG   (2 * ATN_ARR)       // K/V stages start here
#define ATN_STGSZ (4 * ATN_ARR)       // Kh | Kl | Vh | Vl
#define ATN_SMEM  (ATN_STG + 2 * ATN_STGSZ)   // 92160 B

__global__ __launch_bounds__(128, 2)
void attn_mma() {
    extern __shared__ char smc[];
    uint32_t sb = smem_u32(smc);
    const int qt = blockIdx.x, h = blockIdx.y, b = blockIdx.z;
    const int tid = threadIdx.x, lane = tid & 31, w = tid >> 5;
    const int g = lane >> 2, qd = lane & 3;
    const int r8 = lane & 7;

    // ---- async-load Q tile (hi/lo) ----
    {
        const char* srcH = (const char*)g_Qh + (size_t)(b * SEQ + qt * 64) * 2304 + h * 128;
        const char* srcL = (const char*)g_Ql + (size_t)(b * SEQ + qt * 64) * 2304 + h * 128;
#pragma unroll
        for (int j = 0; j < 4; j++) {
            int lin = j * 128 + tid, row = lin >> 3, ch = lin & 7;
            CP_ASYNC16(sb + ATN_SQH + row * AROWB + ch * 16,
                       srcH + (size_t)row * 2304 + ch * 16);
            CP_ASYNC16(sb + ATN_SQL + row * AROWB + ch * 16,
                       srcL + (size_t)row * 2304 + ch * 16);
        }
    }

    auto load_kv = [&](int s, int kt) {
        size_t kb = (size_t)(b * SEQ + kt * 64) * 2304;
        uint32_t st = sb + ATN_STG + s * ATN_STGSZ;
#pragma unroll
        for (int j = 0; j < 16; j++) {
            int arr = j >> 2, lin = (j & 3) * 128 + tid;
            int row = lin >> 3, ch = lin & 7;
            const char* base = (arr == 0) ? (const char*)g_Qh + 2048
                             : (arr == 1) ? (const char*)g_Ql + 2048
                             : (arr == 2) ? (const char*)g_Qh + 2176
                                          : (const char*)g_Ql + 2176;
            CP_ASYNC16(st + arr * ATN_ARR + row * AROWB + ch * 16,
                       base + kb + (size_t)row * 2304 + ch * 16);
        }
    };

    int ktlo = qt - 4; if (ktlo < 0) ktlo = 0;
    int kthi = qt + 4; if (kthi > SEQ / 64 - 1) kthi = SEQ / 64 - 1;

    load_kv(0, ktlo); CP_COMMIT();
    if (ktlo < kthi) { load_kv(1, ktlo + 1); CP_COMMIT(); }

    uint32_t qh[4][4], ql[4][4];
    float oacc[8][4];
#pragma unroll
    for (int i = 0; i < 8; i++)
#pragma unroll
        for (int j = 0; j < 4; j++) oacc[i][j] = 0.f;
    float m0 = -1e30f, m1 = -1e30f, l0 = 0.f, l1 = 0.f;

    for (int kt = ktlo; kt <= kthi; kt++) {
        int s = (kt - ktlo) & 1;
        if (kt < kthi) CP_WAIT1(); else CP_WAIT0();
        __syncthreads();

        if (kt == ktlo) {
            // Q A-frags, resident for the whole kernel
#pragma unroll
            for (int ks = 0; ks < 4; ks++) {
                uint32_t off = (uint32_t)((w * 16 + (lane & 15)) * AROWB +
                                          ks * 32 + (lane >> 4) * 16);
                LDSM_X4(qh[ks][0], qh[ks][1], qh[ks][2], qh[ks][3], sb + ATN_SQH + off);
                LDSM_X4(ql[ks][0], ql[ks][1], ql[ks][2], ql[ks][3], sb + ATN_SQL + off);
            }
        }

        uint32_t stg = sb + ATN_STG + s * ATN_STGSZ;
        uint32_t pKh = stg, pKl = stg + ATN_ARR;
        uint32_t pVh = stg + 2 * ATN_ARR, pVl = stg + 3 * ATN_ARR;

        // ---- S = Q @ K^T (hi/lo split) ----
        float sacc[8][4];
#pragma unroll
        for (int i = 0; i < 8; i++)
#pragma unroll
            for (int j = 0; j < 4; j++) sacc[i][j] = 0.f;

#pragma unroll
        for (int ks = 0; ks < 4; ks++)
#pragma unroll
            for (int sg = 0; sg < 4; sg++) {
                uint32_t off = (uint32_t)((sg * 16 + ((lane >> 4) & 1) * 8 + r8) * AROWB +
                                          ks * 32 + ((lane >> 3) & 1) * 16);
                uint32_t kh0, kh1, kh2, kh3, kl0, kl1, kl2, kl3;
                LDSM_X4(kh0, kh1, kh2, kh3, pKh + off);
                LDSM_X4(kl0, kl1, kl2, kl3, pKl + off);
                mma16816(sacc[sg * 2],     qh[ks], kh0, kh1);
                mma16816(sacc[sg * 2],     qh[ks], kl0, kl1);
                mma16816(sacc[sg * 2],     ql[ks], kh0, kh1);
                mma16816(sacc[sg * 2 + 1], qh[ks], kh2, kh3);
                mma16816(sacc[sg * 2 + 1], qh[ks], kl2, kl3);
                mma16816(sacc[sg * 2 + 1], ql[ks], kh2, kh3);
            }

        // ---- scale + (boundary-only) mask ----
        int rel = kt - qt;
#pragma unroll
        for (int nt = 0; nt < 8; nt++)
#pragma unroll
            for (int e = 0; e < 4; e++) sacc[nt][e] *= 0.125f;
        if (rel == 4 || rel == -4) {
#pragma unroll
            for (int nt = 0; nt < 8; nt++)
#pragma unroll
                for (int e = 0; e < 4; e++) {
                    int ri = w * 16 + g + ((e >= 2) ? 8 : 0);
                    int cj = nt * 8 + 2 * qd + (e & 1);
                    bool ok = (rel == 4) ? (cj <= ri) : (cj >= ri);
                    if (!ok) sacc[nt][e] = -1e30f;
                }
        }

        // ---- online softmax ----
        float rm0 = -1e30f, rm1 = -1e30f;
#pragma unroll
        for (int nt = 0; nt < 8; nt++) {
            rm0 = fmaxf(rm0, fmaxf(sacc[nt][0], sacc[nt][1]));
            rm1 = fmaxf(rm1, fmaxf(sacc[nt][2], sacc[nt][3]));
        }
        rm0 = fmaxf(rm0, __shfl_xor_sync(0xffffffffu, rm0, 1));
        rm0 = fmaxf(rm0, __shfl_xor_sync(0xffffffffu, rm0, 2));
        rm1 = fmaxf(rm1, __shfl_xor_sync(0xffffffffu, rm1, 1));
        rm1 = fmaxf(rm1, __shfl_xor_sync(0xffffffffu, rm1, 2));
        float nm0 = fmaxf(m0, rm0), nm1 = fmaxf(m1, rm1);
        float c0 = __expf(m0 - nm0), c1 = __expf(m1 - nm1);
        m0 = nm0; m1 = nm1;

        float sum0 = 0.f, sum1 = 0.f;
#pragma unroll
        for (int nt = 0; nt < 8; nt++) {
            sacc[nt][0] = __expf(sacc[nt][0] - nm0);
            sacc[nt][1] = __expf(sacc[nt][1] - nm0);
            sacc[nt][2] = __expf(sacc[nt][2] - nm1);
            sacc[nt][3] = __expf(sacc[nt][3] - nm1);
            sum0 += sacc[nt][0] + sacc[nt][1];
            sum1 += sacc[nt][2] + sacc[nt][3];
        }
        sum0 += __shfl_xor_sync(0xffffffffu, sum0, 1);
        sum0 += __shfl_xor_sync(0xffffffffu, sum0, 2);
        sum1 += __shfl_xor_sync(0xffffffffu, sum1, 1);
        sum1 += __shfl_xor_sync(0xffffffffu, sum1, 2);
        l0 = l0 * c0 + sum0; l1 = l1 * c1 + sum1;
#pragma unroll
        for (int nt = 0; nt < 8; nt++) {
            oacc[nt][0] *= c0; oacc[nt][1] *= c0;
            oacc[nt][2] *= c1; oacc[nt][3] *= c1;
        }

        // ---- P frags (hi/lo) from S accumulators ----
        uint32_t ph[4][4], pl[4][4];
#pragma unroll
        for (int kg = 0; kg < 4; kg++) {
            split2(sacc[2 * kg][0],     sacc[2 * kg][1],     ph[kg][0], pl[kg][0]);
            split2(sacc[2 * kg][2],     sacc[2 * kg][3],     ph[kg][1], pl[kg][1]);
            split2(sacc[2 * kg + 1][0], sacc[2 * kg + 1][1], ph[kg][2], pl[kg][2]);
            split2(sacc[2 * kg + 1][2], sacc[2 * kg + 1][3], ph[kg][3], pl[kg][3]);
        }

        // ---- O += P @ V (hi/lo split) ----
#pragma unroll
        for (int kg = 0; kg < 4; kg++)
#pragma unroll
            for (int dg = 0; dg < 4; dg++) {
                uint32_t off = (uint32_t)((kg * 16 + ((lane >> 3) & 1) * 8 + r8) * AROWB +
                                          dg * 32 + ((lane >> 4) & 1) * 16);
                uint32_t vh0, vh1, vh2, vh3, vl0, vl1, vl2, vl3;
                LDSM_X4T(vh0, vh1, vh2, vh3, pVh + off);
                LDSM_X4T(vl0, vl1, vl2, vl3, pVl + off);
                mma16816(oacc[dg * 2],     ph[kg], vh0, vh1);
                mma16816(oacc[dg * 2],     ph[kg], vl0, vl1);
                mma16816(oacc[dg * 2],     pl[kg], vh0, vh1);
                mma16816(oacc[dg * 2 + 1], ph[kg], vh2, vh3);
                mma16816(oacc[dg * 2 + 1], ph[kg], vl2, vl3);
                mma16816(oacc[dg * 2 + 1], pl[kg], vh2, vh3);
            }

        __syncthreads();
        if (kt + 2 <= kthi) { load_kv(s, kt + 2); CP_COMMIT(); }
    }

    // ---- finalize: /l, split hi/lo, store ----
    float inv0 = 1.0f / l0, inv1 = 1.0f / l1;
    size_t row0 = (size_t)(b * SEQ + qt * 64 + w * 16 + g);
    size_t row1 = row0 + 8;
#pragma unroll
    for (int nt = 0; nt < 8; nt++) {
        int col = h * 64 + nt * 8 + 2 * qd;
        uint32_t hi, lo;
        split2(oacc[nt][0] * inv0, oacc[nt][1] * inv0, hi, lo);
        *(uint32_t*)&g_Oh[row0 * WIDTH + col] = hi;
        *(uint32_t*)&g_Ol[row0 * WIDTH + col] = lo;
        split2(oacc[nt][2] * inv1, oacc[nt][3] * inv1, hi, lo);
        *(uint32_t*)&g_Oh[row1 * WIDTH + col] = hi;
        *(uint32_t*)&g_Ol[row1 * WIDTH + col] = lo;
    }
}

// ---------------------------------------------------------------------------
// Launch
// ---------------------------------------------------------------------------
extern "C" void kernel_launch(void* const* d_in, const int* in_sizes, int n_in,
                              void* d_out, int out_size) {
    const float* x  = (const float*)d_in[0];
    const float* Wq = (const float*)d_in[1];
    const float* Wk = (const float*)d_in[2];
    const float* Wv = (const float*)d_in[3];
    const float* Wf = (const float*)d_in[4];
    const float* bf = (const float*)d_in[5];
    float* out = (float*)d_out;
    (void)in_sizes; (void)n_in; (void)out_size;

    __nv_bfloat16 *pAh, *pAl, *pWh, *pWl, *pFh, *pFl, *pQh, *pQl, *pOh, *pOl;
    cudaGetSymbolAddress((void**)&pAh, g_Ah);
    cudaGetSymbolAddress((void**)&pAl, g_Al);
    cudaGetSymbolAddress((void**)&pWh, g_Wh);
    cudaGetSymbolAddress((void**)&pWl, g_Wl);
    cudaGetSymbolAddress((void**)&pFh, g_Fh);
    cudaGetSymbolAddress((void**)&pFl, g_Fl);
    cudaGetSymbolAddress((void**)&pQh, g_Qh);
    cudaGetSymbolAddress((void**)&pQl, g_Ql);
    cudaGetSymbolAddress((void**)&pOh, g_Oh);
    cudaGetSymbolAddress((void**)&pOl, g_Ol);

    cudaFuncSetAttribute(mmagemm,
                         cudaFuncAttributeMaxDynamicSharedMemorySize, GEMM_SMEM);
    cudaFuncSetAttribute(attn_mma,
                         cudaFuncAttributeMaxDynamicSharedMemorySize, ATN_SMEM);

    convert_hl<<<TOK * WIDTH / 1024, 256>>>(x, pAh, pAl, TOK * WIDTH);
    convert_w<<<NQKV, 256>>>(Wq, Wk, Wv);
    convert_hl<<<WIDTH * WIDTH / 1024, 256>>>(Wf, pFh, pFl, WIDTH * WIDTH);

    // QKV projection -> bf16 hi/lo qkv
    mmagemm<<<dim3(NQKV / 128, TOK / 128), 256, GEMM_SMEM>>>(
        pAh, pAl, pWh, pWl, nullptr, pQh, pQl, TOK, NQKV, WIDTH, nullptr);

    // tensor-core windowed attention -> bf16 hi/lo O
    attn_mma<<<dim3(SEQ / 64, NH, BATCH), 128, ATN_SMEM>>>();

    // output projection + bias -> fp32 out
    mmagemm<<<dim3(WIDTH / 128, TOK / 128), 256, GEMM_SMEM>>>(
        pOh, pOl, pFh, pFl, out, nullptr, nullptr, TOK, WIDTH, WIDTH, bf);
}

// round 5
// speedup vs baseline: 2.5546x; 1.0906x over previous
#include <cuda_runtime.h>
#include <cuda_bf16.h>
#include <cstdint>
#include <math.h>

// Problem constants
#define SEQ    2048
#define BATCH  2
#define WIDTH  1024
#define NH     16
#define HD     64
#define WIN    256
#define TOK    (BATCH*SEQ)     // 4096
#define NQKV   1152            // 1024 q + 64 k + 64 v

// ---------------------------------------------------------------------------
// Scratch (device globals; no allocation allowed)
// ---------------------------------------------------------------------------
__device__ __nv_bfloat16 g_Ah[TOK * WIDTH],  g_Al[TOK * WIDTH];    // x hi/lo
__device__ __nv_bfloat16 g_Wh[NQKV * WIDTH], g_Wl[NQKV * WIDTH];   // [Wq;Wk;Wv] hi/lo
__device__ __nv_bfloat16 g_Fh[WIDTH * WIDTH], g_Fl[WIDTH * WIDTH]; // Wf hi/lo
__device__ __nv_bfloat16 g_Qh[TOK * NQKV],  g_Ql[TOK * NQKV];      // qkv hi/lo
__device__ __nv_bfloat16 g_Oh[TOK * WIDTH], g_Ol[TOK * WIDTH];     // attn out hi/lo

// ---------------------------------------------------------------------------
// Helpers
// ---------------------------------------------------------------------------
__device__ __forceinline__ uint32_t smem_u32(const void* p) {
    uint32_t a;
    asm("{ .reg .u64 t; cvta.to.shared.u64 t, %1; cvt.u32.u64 %0, t; }"
        : "=r"(a) : "l"(p));
    return a;
}

#define CP_ASYNC16(sa, ga) \
    asm volatile("cp.async.cg.shared.global [%0], [%1], 16;" :: "r"(sa), "l"(ga))
#define CP_COMMIT() asm volatile("cp.async.commit_group;" ::: "memory")
#define CP_WAIT1()  asm volatile("cp.async.wait_group 1;" ::: "memory")
#define CP_WAIT0()  asm volatile("cp.async.wait_group 0;" ::: "memory")

#define LDSM_X4(r0, r1, r2, r3, addr) \
    asm volatile("ldmatrix.sync.aligned.m8n8.x4.shared.b16 {%0,%1,%2,%3}, [%4];" \
        : "=r"(r0), "=r"(r1), "=r"(r2), "=r"(r3) : "r"(addr))
#define LDSM_X4T(r0, r1, r2, r3, addr) \
    asm volatile("ldmatrix.sync.aligned.m8n8.x4.trans.shared.b16 {%0,%1,%2,%3}, [%4];" \
        : "=r"(r0), "=r"(r1), "=r"(r2), "=r"(r3) : "r"(addr))

__device__ __forceinline__ void mma16816(float* c, const uint32_t* a,
                                         uint32_t b0, uint32_t b1) {
    asm volatile(
        "mma.sync.aligned.m16n8k16.row.col.f32.bf16.bf16.f32 "
        "{%0,%1,%2,%3}, {%4,%5,%6,%7}, {%8,%9}, {%0,%1,%2,%3};"
        : "+f"(c[0]), "+f"(c[1]), "+f"(c[2]), "+f"(c[3])
        : "r"(a[0]), "r"(a[1]), "r"(a[2]), "r"(a[3]), "r"(b0), "r"(b1));
}

__device__ __forceinline__ uint32_t packbf(__nv_bfloat16 a, __nv_bfloat16 b) {
    __nv_bfloat162 t; t.x = a; t.y = b;
    return *(uint32_t*)&t;
}
__device__ __forceinline__ void split2(float a, float b, uint32_t& hi, uint32_t& lo) {
    __nv_bfloat16 ah = __float2bfloat16(a), bh = __float2bfloat16(b);
    hi = packbf(ah, bh);
    lo = packbf(__float2bfloat16(a - __bfloat162float(ah)),
                __float2bfloat16(b - __bfloat162float(bh)));
}
__device__ __forceinline__ void split_bf16(float v, __nv_bfloat16& h, __nv_bfloat16& l) {
    h = __float2bfloat16(v);
    l = __float2bfloat16(v - __bfloat162float(h));
}

// ---------------------------------------------------------------------------
// fp32 -> bf16 hi/lo conversions
// ---------------------------------------------------------------------------
__global__ void convert_hl(const float* __restrict__ src,
                           __nv_bfloat16* __restrict__ hi,
                           __nv_bfloat16* __restrict__ lo, int n) {
    int i = (blockIdx.x * blockDim.x + threadIdx.x) * 4;
    if (i >= n) return;
    float4 v = *(const float4*)(src + i);
    __nv_bfloat16 h0, h1, h2, h3, l0, l1, l2, l3;
    split_bf16(v.x, h0, l0); split_bf16(v.y, h1, l1);
    split_bf16(v.z, h2, l2); split_bf16(v.w, h3, l3);
    __nv_bfloat162* H = (__nv_bfloat162*)(hi + i);
    __nv_bfloat162* L = (__nv_bfloat162*)(lo + i);
    H[0] = __nv_bfloat162(h0, h1); H[1] = __nv_bfloat162(h2, h3);
    L[0] = __nv_bfloat162(l0, l1); L[1] = __nv_bfloat162(l2, l3);
}

__global__ void convert_w(const float* __restrict__ Wq, const float* __restrict__ Wk,
                          const float* __restrict__ Wv) {
    int row = blockIdx.x;
    const float* src;
    if (row < 1024)      src = Wq + (size_t)row * WIDTH;
    else if (row < 1088) src = Wk + (size_t)(row - 1024) * WIDTH;
    else                 src = Wv + (size_t)(row - 1088) * WIDTH;
    int c = threadIdx.x * 4;
    float4 v = *(const float4*)(src + c);
    __nv_bfloat16 h0, h1, h2, h3, l0, l1, l2, l3;
    split_bf16(v.x, h0, l0); split_bf16(v.y, h1, l1);
    split_bf16(v.z, h2, l2); split_bf16(v.w, h3, l3);
    size_t base = (size_t)row * WIDTH + c;
    __nv_bfloat162* H = (__nv_bfloat162*)(g_Wh + base);
    __nv_bfloat162* L = (__nv_bfloat162*)(g_Wl + base);
    H[0] = __nv_bfloat162(h0, h1); H[1] = __nv_bfloat162(h2, h3);
    L[0] = __nv_bfloat162(l0, l1); L[1] = __nv_bfloat162(l2, l3);
}

// ---------------------------------------------------------------------------
// mma.sync GEMM: C = A @ B^T (+bias), bf16 hi/lo split, 128x128x32 tile,
// 8 warps, 2-stage cp.async pipeline, 2 CTAs/SM (regs capped at 128).
// ---------------------------------------------------------------------------
#define BK 32
#define ROWB 80
#define ARR_B (128 * ROWB)
#define STAGE_B (4 * ARR_B)
#define GEMM_SMEM (2 * STAGE_B)       // 81920 B -> 2 CTAs/SM

__global__ __launch_bounds__(256, 2)
void mmagemm(const __nv_bfloat16* __restrict__ Ah, const __nv_bfloat16* __restrict__ Al,
             const __nv_bfloat16* __restrict__ Bh, const __nv_bfloat16* __restrict__ Bl,
             float* __restrict__ C,
             __nv_bfloat16* __restrict__ Ch, __nv_bfloat16* __restrict__ Cl,
             int M, int N, int K, const float* __restrict__ bias) {
    extern __shared__ char smem[];
    uint32_t sb = smem_u32(smem);
    const int tid  = threadIdx.x;
    const int lane = tid & 31;
    const int wid  = tid >> 5;
    const int wm   = wid >> 2;
    const int wn   = wid & 3;
    const int m0 = blockIdx.y * 128;
    const int n0 = blockIdx.x * 128;
    const int NK = K / BK;
    const size_t RS = (size_t)K * 2;

    const int crow = tid >> 1;
    const int ccol = (tid & 1) * 2;
    const uint32_t s_off0 = crow * ROWB + ccol * 16;
    const char* gA0 = (const char*)Ah + (size_t)(m0 + crow) * RS + ccol * 16;
    const char* gA1 = (const char*)Al + (size_t)(m0 + crow) * RS + ccol * 16;
    const char* gB0 = (const char*)Bh + (size_t)(n0 + crow) * RS + ccol * 16;
    const char* gB1 = (const char*)Bl + (size_t)(n0 + crow) * RS + ccol * 16;

    auto load_stage = [&](int s, int it) {
        uint32_t st = sb + s * STAGE_B;
        size_t kb = (size_t)it * (BK * 2);
        CP_ASYNC16(st + 0 * ARR_B + s_off0,      gA0 + kb);
        CP_ASYNC16(st + 0 * ARR_B + s_off0 + 16, gA0 + kb + 16);
        CP_ASYNC16(st + 1 * ARR_B + s_off0,      gA1 + kb);
        CP_ASYNC16(st + 1 * ARR_B + s_off0 + 16, gA1 + kb + 16);
        CP_ASYNC16(st + 2 * ARR_B + s_off0,      gB0 + kb);
        CP_ASYNC16(st + 2 * ARR_B + s_off0 + 16, gB0 + kb + 16);
        CP_ASYNC16(st + 3 * ARR_B + s_off0,      gB1 + kb);
        CP_ASYNC16(st + 3 * ARR_B + s_off0 + 16, gB1 + kb + 16);
    };

    float acc[4][4][4];
#pragma unroll
    for (int i = 0; i < 4; i++)
#pragma unroll
        for (int j = 0; j < 4; j++)
#pragma unroll
            for (int q = 0; q < 4; q++) acc[i][j][q] = 0.f;

    const int asub = lane >> 3;
    const int a_row_in = (lane & 7) + 8 * (asub & 1);
    const int a_chunk  = asub >> 1;
    const int b_row_in = (lane & 7) + 8 * (asub >> 1);
    const int b_chunk  = asub & 1;

    load_stage(0, 0); CP_COMMIT();

    for (int it = 0; it < NK; ++it) {
        if (it + 1 < NK) { load_stage((it + 1) & 1, it + 1); CP_COMMIT(); CP_WAIT1(); }
        else             { CP_WAIT0(); }
        __syncthreads();

        uint32_t st  = sb + (it & 1) * STAGE_B;
        uint32_t pAh = st;
        uint32_t pAl = st + ARR_B;
        uint32_t pBh = st + 2 * ARR_B;
        uint32_t pBl = st + 3 * ARR_B;

#pragma unroll
        for (int kk = 0; kk < 2; kk++) {
            uint32_t ah[4][4], al[4][4], bh[2][4], bl[2][4];
#pragma unroll
            for (int mt = 0; mt < 4; mt++) {
                uint32_t off = (uint32_t)((wm * 64 + mt * 16 + a_row_in) * ROWB +
                                          (kk * 2 + a_chunk) * 16);
                LDSM_X4(ah[mt][0], ah[mt][1], ah[mt][2], ah[mt][3], pAh + off);
                LDSM_X4(al[mt][0], al[mt][1], al[mt][2], al[mt][3], pAl + off);
            }
#pragma unroll
            for (int p = 0; p < 2; p++) {
                uint32_t off = (uint32_t)((wn * 32 + p * 16 + b_row_in) * ROWB +
                                          (kk * 2 + b_chunk) * 16);
                LDSM_X4(bh[p][0], bh[p][1], bh[p][2], bh[p][3], pBh + off);
                LDSM_X4(bl[p][0], bl[p][1], bl[p][2], bl[p][3], pBl + off);
            }
#pragma unroll
            for (int mt = 0; mt < 4; mt++)
#pragma unroll
                for (int p = 0; p < 2; p++)
#pragma unroll
                    for (int hh = 0; hh < 2; hh++) {
                        int nt = p * 2 + hh;
                        mma16816(acc[mt][nt], ah[mt], bh[p][hh * 2], bh[p][hh * 2 + 1]);
                        mma16816(acc[mt][nt], ah[mt], bl[p][hh * 2], bl[p][hh * 2 + 1]);
                        mma16816(acc[mt][nt], al[mt], bh[p][hh * 2], bh[p][hh * 2 + 1]);
                    }
        }
        __syncthreads();
    }

    const int gid = lane >> 2;
    const int qid = lane & 3;
#pragma unroll
    for (int mt = 0; mt < 4; mt++) {
        int r0 = m0 + wm * 64 + mt * 16 + gid;
#pragma unroll
        for (int nt = 0; nt < 4; nt++) {
            int c = n0 + wn * 32 + nt * 8 + qid * 2;
            if (C) {
                float b0 = 0.f, b1 = 0.f;
                if (bias) { b0 = bias[c]; b1 = bias[c + 1]; }
                *(float2*)&C[(size_t)r0 * N + c] =
                    make_float2(acc[mt][nt][0] + b0, acc[mt][nt][1] + b1);
                *(float2*)&C[(size_t)(r0 + 8) * N + c] =
                    make_float2(acc[mt][nt][2] + b0, acc[mt][nt][3] + b1);
            } else {
                uint32_t hi, lo;
                split2(acc[mt][nt][0], acc[mt][nt][1], hi, lo);
                *(uint32_t*)&Ch[(size_t)r0 * N + c] = hi;
                *(uint32_t*)&Cl[(size_t)r0 * N + c] = lo;
                split2(acc[mt][nt][2], acc[mt][nt][3], hi, lo);
                *(uint32_t*)&Ch[(size_t)(r0 + 8) * N + c] = hi;
                *(uint32_t*)&Cl[(size_t)(r0 + 8) * N + c] = lo;
            }
        }
    }
}

// ---------------------------------------------------------------------------
// Tensor-core windowed MQA flash attention (as R4).
// ---------------------------------------------------------------------------
#define AROWB 144
#define ATN_ARR   (64 * AROWB)
#define ATN_SQH   0
#define ATN_SQL   ATN_ARR
#define ATN_STG   (2 * ATN_ARR)
#define ATN_STGSZ (4 * ATN_ARR)
#define ATN_SMEM  (ATN_STG + 2 * ATN_STGSZ)   // 92160 B

__global__ __launch_bounds__(128, 2)
void attn_mma() {
    extern __shared__ char smc[];
    uint32_t sb = smem_u32(smc);
    const int qt = blockIdx.x, h = blockIdx.y, b = blockIdx.z;
    const int tid = threadIdx.x, lane = tid & 31, w = tid >> 5;
    const int g = lane >> 2, qd = lane & 3;
    const int r8 = lane & 7;

    {
        const char* srcH = (const char*)g_Qh + (size_t)(b * SEQ + qt * 64) * 2304 + h * 128;
        const char* srcL = (const char*)g_Ql + (size_t)(b * SEQ + qt * 64) * 2304 + h * 128;
#pragma unroll
        for (int j = 0; j < 4; j++) {
            int lin = j * 128 + tid, row = lin >> 3, ch = lin & 7;
            CP_ASYNC16(sb + ATN_SQH + row * AROWB + ch * 16,
                       srcH + (size_t)row * 2304 + ch * 16);
            CP_ASYNC16(sb + ATN_SQL + row * AROWB + ch * 16,
                       srcL + (size_t)row * 2304 + ch * 16);
        }
    }

    auto load_kv = [&](int s, int kt) {
        size_t kb = (size_t)(b * SEQ + kt * 64) * 2304;
        uint32_t st = sb + ATN_STG + s * ATN_STGSZ;
#pragma unroll
        for (int j = 0; j < 16; j++) {
            int arr = j >> 2, lin = (j & 3) * 128 + tid;
            int row = lin >> 3, ch = lin & 7;
            const char* base = (arr == 0) ? (const char*)g_Qh + 2048
                             : (arr == 1) ? (const char*)g_Ql + 2048
                             : (arr == 2) ? (const char*)g_Qh + 2176
                                          : (const char*)g_Ql + 2176;
            CP_ASYNC16(st + arr * ATN_ARR + row * AROWB + ch * 16,
                       base + kb + (size_t)row * 2304 + ch * 16);
        }
    };

    int ktlo = qt - 4; if (ktlo < 0) ktlo = 0;
    int kthi = qt + 4; if (kthi > SEQ / 64 - 1) kthi = SEQ / 64 - 1;

    load_kv(0, ktlo); CP_COMMIT();
    if (ktlo < kthi) { load_kv(1, ktlo + 1); CP_COMMIT(); }

    uint32_t qh[4][4], ql[4][4];
    float oacc[8][4];
#pragma unroll
    for (int i = 0; i < 8; i++)
#pragma unroll
        for (int j = 0; j < 4; j++) oacc[i][j] = 0.f;
    float m0 = -1e30f, m1 = -1e30f, l0 = 0.f, l1 = 0.f;

    for (int kt = ktlo; kt <= kthi; kt++) {
        int s = (kt - ktlo) & 1;
        if (kt < kthi) CP_WAIT1(); else CP_WAIT0();
        __syncthreads();

        if (kt == ktlo) {
#pragma unroll
            for (int ks = 0; ks < 4; ks++) {
                uint32_t off = (uint32_t)((w * 16 + (lane & 15)) * AROWB +
                                          ks * 32 + (lane >> 4) * 16);
                LDSM_X4(qh[ks][0], qh[ks][1], qh[ks][2], qh[ks][3], sb + ATN_SQH + off);
                LDSM_X4(ql[ks][0], ql[ks][1], ql[ks][2], ql[ks][3], sb + ATN_SQL + off);
            }
        }

        uint32_t stg = sb + ATN_STG + s * ATN_STGSZ;
        uint32_t pKh = stg, pKl = stg + ATN_ARR;
        uint32_t pVh = stg + 2 * ATN_ARR, pVl = stg + 3 * ATN_ARR;

        float sacc[8][4];
#pragma unroll
        for (int i = 0; i < 8; i++)
#pragma unroll
            for (int j = 0; j < 4; j++) sacc[i][j] = 0.f;

#pragma unroll
        for (int ks = 0; ks < 4; ks++)
#pragma unroll
            for (int sg = 0; sg < 4; sg++) {
                uint32_t off = (uint32_t)((sg * 16 + ((lane >> 4) & 1) * 8 + r8) * AROWB +
                                          ks * 32 + ((lane >> 3) & 1) * 16);
                uint32_t kh0, kh1, kh2, kh3, kl0, kl1, kl2, kl3;
                LDSM_X4(kh0, kh1, kh2, kh3, pKh + off);
                LDSM_X4(kl0, kl1, kl2, kl3, pKl + off);
                mma16816(sacc[sg * 2],     qh[ks], kh0, kh1);
                mma16816(sacc[sg * 2],     qh[ks], kl0, kl1);
                mma16816(sacc[sg * 2],     ql[ks], kh0, kh1);
                mma16816(sacc[sg * 2 + 1], qh[ks], kh2, kh3);
                mma16816(sacc[sg * 2 + 1], qh[ks], kl2, kl3);
                mma16816(sacc[sg * 2 + 1], ql[ks], kh2, kh3);
            }

        int rel = kt - qt;
#pragma unroll
        for (int nt = 0; nt < 8; nt++)
#pragma unroll
            for (int e = 0; e < 4; e++) sacc[nt][e] *= 0.125f;
        if (rel == 4 || rel == -4) {
#pragma unroll
            for (int nt = 0; nt < 8; nt++)
#pragma unroll
                for (int e = 0; e < 4; e++) {
                    int ri = w * 16 + g + ((e >= 2) ? 8 : 0);
                    int cj = nt * 8 + 2 * qd + (e & 1);
                    bool ok = (rel == 4) ? (cj <= ri) : (cj >= ri);
                    if (!ok) sacc[nt][e] = -1e30f;
                }
        }

        float rm0 = -1e30f, rm1 = -1e30f;
#pragma unroll
        for (int nt = 0; nt < 8; nt++) {
            rm0 = fmaxf(rm0, fmaxf(sacc[nt][0], sacc[nt][1]));
            rm1 = fmaxf(rm1, fmaxf(sacc[nt][2], sacc[nt][3]));
        }
        rm0 = fmaxf(rm0, __shfl_xor_sync(0xffffffffu, rm0, 1));
        rm0 = fmaxf(rm0, __shfl_xor_sync(0xffffffffu, rm0, 2));
        rm1 = fmaxf(rm1, __shfl_xor_sync(0xffffffffu, rm1, 1));
        rm1 = fmaxf(rm1, __shfl_xor_sync(0xffffffffu, rm1, 2));
        float nm0 = fmaxf(m0, rm0), nm1 = fmaxf(m1, rm1);
        float c0 = __expf(m0 - nm0), c1 = __expf(m1 - nm1);
        m0 = nm0; m1 = nm1;

        float sum0 = 0.f, sum1 = 0.f;
#pragma unroll
        for (int nt = 0; nt < 8; nt++) {
            sacc[nt][0] = __expf(sacc[nt][0] - nm0);
            sacc[nt][1] = __expf(sacc[nt][1] - nm0);
            sacc[nt][2] = __expf(sacc[nt][2] - nm1);
            sacc[nt][3] = __expf(sacc[nt][3] - nm1);
            sum0 += sacc[nt][0] + sacc[nt][1];
            sum1 += sacc[nt][2] + sacc[nt][3];
        }
        sum0 += __shfl_xor_sync(0xffffffffu, sum0, 1);
        sum0 += __shfl_xor_sync(0xffffffffu, sum0, 2);
        sum1 += __shfl_xor_sync(0xffffffffu, sum1, 1);
        sum1 += __shfl_xor_sync(0xffffffffu, sum1, 2);
        l0 = l0 * c0 + sum0; l1 = l1 * c1 + sum1;
#pragma unroll
        for (int nt = 0; nt < 8; nt++) {
            oacc[nt][0] *= c0; oacc[nt][1] *= c0;
            oacc[nt][2] *= c1; oacc[nt][3] *= c1;
        }

        uint32_t ph[4][4], pl[4][4];
#pragma unroll
        for (int kg = 0; kg < 4; kg++) {
            split2(sacc[2 * kg][0],     sacc[2 * kg][1],     ph[kg][0], pl[kg][0]);
            split2(sacc[2 * kg][2],     sacc[2 * kg][3],     ph[kg][1], pl[kg][1]);
            split2(sacc[2 * kg + 1][0], sacc[2 * kg + 1][1], ph[kg][2], pl[kg][2]);
            split2(sacc[2 * kg + 1][2], sacc[2 * kg + 1][3], ph[kg][3], pl[kg][3]);
        }

#pragma unroll
        for (int kg = 0; kg < 4; kg++)
#pragma unroll
            for (int dg = 0; dg < 4; dg++) {
                uint32_t off = (uint32_t)((kg * 16 + ((lane >> 3) & 1) * 8 + r8) * AROWB +
                                          dg * 32 + ((lane >> 4) & 1) * 16);
                uint32_t vh0, vh1, vh2, vh3, vl0, vl1, vl2, vl3;
                LDSM_X4T(vh0, vh1, vh2, vh3, pVh + off);
                LDSM_X4T(vl0, vl1, vl2, vl3, pVl + off);
                mma16816(oacc[dg * 2],     ph[kg], vh0, vh1);
                mma16816(oacc[dg * 2],     ph[kg], vl0, vl1);
                mma16816(oacc[dg * 2],     pl[kg], vh0, vh1);
                mma16816(oacc[dg * 2 + 1], ph[kg], vh2, vh3);
                mma16816(oacc[dg * 2 + 1], ph[kg], vl2, vl3);
                mma16816(oacc[dg * 2 + 1], pl[kg], vh2, vh3);
            }

        __syncthreads();
        if (kt + 2 <= kthi) { load_kv(s, kt + 2); CP_COMMIT(); }
    }

    float inv0 = 1.0f / l0, inv1 = 1.0f / l1;
    size_t row0 = (size_t)(b * SEQ + qt * 64 + w * 16 + g);
    size_t row1 = row0 + 8;
#pragma unroll
    for (int nt = 0; nt < 8; nt++) {
        int col = h * 64 + nt * 8 + 2 * qd;
        uint32_t hi, lo;
        split2(oacc[nt][0] * inv0, oacc[nt][1] * inv0, hi, lo);
        *(uint32_t*)&g_Oh[row0 * WIDTH + col] = hi;
        *(uint32_t*)&g_Ol[row0 * WIDTH + col] = lo;
        split2(oacc[nt][2] * inv1, oacc[nt][3] * inv1, hi, lo);
        *(uint32_t*)&g_Oh[row1 * WIDTH + col] = hi;
        *(uint32_t*)&g_Ol[row1 * WIDTH + col] = lo;
    }
}

// ---------------------------------------------------------------------------
// Launch
// ---------------------------------------------------------------------------
extern "C" void kernel_launch(void* const* d_in, const int* in_sizes, int n_in,
                              void* d_out, int out_size) {
    const float* x  = (const float*)d_in[0];
    const float* Wq = (const float*)d_in[1];
    const float* Wk = (const float*)d_in[2];
    const float* Wv = (const float*)d_in[3];
    const float* Wf = (const float*)d_in[4];
    const float* bf = (const float*)d_in[5];
    float* out = (float*)d_out;
    (void)in_sizes; (void)n_in; (void)out_size;

    __nv_bfloat16 *pAh, *pAl, *pWh, *pWl, *pFh, *pFl, *pQh, *pQl, *pOh, *pOl;
    cudaGetSymbolAddress((void**)&pAh, g_Ah);
    cudaGetSymbolAddress((void**)&pAl, g_Al);
    cudaGetSymbolAddress((void**)&pWh, g_Wh);
    cudaGetSymbolAddress((void**)&pWl, g_Wl);
    cudaGetSymbolAddress((void**)&pFh, g_Fh);
    cudaGetSymbolAddress((void**)&pFl, g_Fl);
    cudaGetSymbolAddress((void**)&pQh, g_Qh);
    cudaGetSymbolAddress((void**)&pQl, g_Ql);
    cudaGetSymbolAddress((void**)&pOh, g_Oh);
    cudaGetSymbolAddress((void**)&pOl, g_Ol);

    cudaFuncSetAttribute(mmagemm,
                         cudaFuncAttributeMaxDynamicSharedMemorySize, GEMM_SMEM);
    cudaFuncSetAttribute(attn_mma,
                         cudaFuncAttributeMaxDynamicSharedMemorySize, ATN_SMEM);

    convert_hl<<<TOK * WIDTH / 1024, 256>>>(x, pAh, pAl, TOK * WIDTH);
    convert_w<<<NQKV, 256>>>(Wq, Wk, Wv);
    convert_hl<<<WIDTH * WIDTH / 1024, 256>>>(Wf, pFh, pFl, WIDTH * WIDTH);

    // QKV projection -> bf16 hi/lo qkv
    mmagemm<<<dim3(NQKV / 128, TOK / 128), 256, GEMM_SMEM>>>(
        pAh, pAl, pWh, pWl, nullptr, pQh, pQl, TOK, NQKV, WIDTH, nullptr);

    // tensor-core windowed attention -> bf16 hi/lo O
    attn_mma<<<dim3(SEQ / 64, NH, BATCH), 128, ATN_SMEM>>>();

    // output projection + bias -> fp32 out
    mmagemm<<<dim3(WIDTH / 128, TOK / 128), 256, GEMM_SMEM>>>(
        pOh, pOl, pFh, pFl, out, nullptr, nullptr, TOK, WIDTH, WIDTH, bf);
}

// round 6
// speedup vs baseline: 3.1971x; 1.2515x over previous
#include <cuda_runtime.h>
#include <cuda_fp16.h>
#include <cstdint>
#include <math.h>

// Problem constants
#define SEQ    2048
#define BATCH  2
#define WIDTH  1024
#define NH     16
#define HD     64
#define WIN    256
#define TOK    (BATCH*SEQ)     // 4096
#define NQKV   1152            // 1024 q + 64 k + 64 v

// ---------------------------------------------------------------------------
// Scratch (device globals; no allocation allowed).  fp16 split scheme:
// activations: hi+lo (22-bit exact); weights: hi only (2^-12 trunc).
// ---------------------------------------------------------------------------
__device__ __half g_Ah[TOK * WIDTH],  g_Al[TOK * WIDTH];    // x hi/lo
__device__ __half g_Wh[NQKV * WIDTH];                        // [Wq;Wk;Wv] hi
__device__ __half g_Fh[WIDTH * WIDTH];                       // Wf hi
__device__ __half g_Qh[TOK * NQKV],  g_Ql[TOK * NQKV];       // qkv hi/lo
__device__ __half g_Oh[TOK * WIDTH], g_Ol[TOK * WIDTH];      // attn out hi/lo

// ---------------------------------------------------------------------------
// Helpers
// ---------------------------------------------------------------------------
__device__ __forceinline__ uint32_t smem_u32(const void* p) {
    uint32_t a;
    asm("{ .reg .u64 t; cvta.to.shared.u64 t, %1; cvt.u32.u64 %0, t; }"
        : "=r"(a) : "l"(p));
    return a;
}

#define CP_ASYNC16(sa, ga) \
    asm volatile("cp.async.cg.shared.global [%0], [%1], 16;" :: "r"(sa), "l"(ga))
#define CP_COMMIT() asm volatile("cp.async.commit_group;" ::: "memory")
#define CP_WAIT1()  asm volatile("cp.async.wait_group 1;" ::: "memory")
#define CP_WAIT0()  asm volatile("cp.async.wait_group 0;" ::: "memory")

#define LDSM_X4(r0, r1, r2, r3, addr) \
    asm volatile("ldmatrix.sync.aligned.m8n8.x4.shared.b16 {%0,%1,%2,%3}, [%4];" \
        : "=r"(r0), "=r"(r1), "=r"(r2), "=r"(r3) : "r"(addr))
#define LDSM_X4T(r0, r1, r2, r3, addr) \
    asm volatile("ldmatrix.sync.aligned.m8n8.x4.trans.shared.b16 {%0,%1,%2,%3}, [%4];" \
        : "=r"(r0), "=r"(r1), "=r"(r2), "=r"(r3) : "r"(addr))

__device__ __forceinline__ void mma16816(float* c, const uint32_t* a,
                                         uint32_t b0, uint32_t b1) {
    asm volatile(
        "mma.sync.aligned.m16n8k16.row.col.f32.f16.f16.f32 "
        "{%0,%1,%2,%3}, {%4,%5,%6,%7}, {%8,%9}, {%0,%1,%2,%3};"
        : "+f"(c[0]), "+f"(c[1]), "+f"(c[2]), "+f"(c[3])
        : "r"(a[0]), "r"(a[1]), "r"(a[2]), "r"(a[3]), "r"(b0), "r"(b1));
}

__device__ __forceinline__ uint32_t packh(__half a, __half b) {
    __half2 t; t.x = a; t.y = b;
    return *(uint32_t*)&t;
}
__device__ __forceinline__ void split2h(float a, float b, uint32_t& hi, uint32_t& lo) {
    __half ah = __float2half_rn(a), bh = __float2half_rn(b);
    hi = packh(ah, bh);
    lo = packh(__float2half_rn(a - __half2float(ah)),
               __float2half_rn(b - __half2float(bh)));
}
__device__ __forceinline__ void split_h(float v, __half& h, __half& l) {
    h = __float2half_rn(v);
    l = __float2half_rn(v - __half2float(h));
}

// ---------------------------------------------------------------------------
// fp32 -> fp16 conversions
// ---------------------------------------------------------------------------
__global__ void convert_hl(const float* __restrict__ src,
                           __half* __restrict__ hi, __half* __restrict__ lo, int n) {
    int i = (blockIdx.x * blockDim.x + threadIdx.x) * 4;
    if (i >= n) return;
    float4 v = *(const float4*)(src + i);
    __half h0, h1, h2, h3, l0, l1, l2, l3;
    split_h(v.x, h0, l0); split_h(v.y, h1, l1);
    split_h(v.z, h2, l2); split_h(v.w, h3, l3);
    __half2* H = (__half2*)(hi + i);
    __half2* L = (__half2*)(lo + i);
    H[0] = __half2(h0, h1); H[1] = __half2(h2, h3);
    L[0] = __half2(l0, l1); L[1] = __half2(l2, l3);
}

__global__ void convert_h(const float* __restrict__ src,
                          __half* __restrict__ hi, int n) {
    int i = (blockIdx.x * blockDim.x + threadIdx.x) * 4;
    if (i >= n) return;
    float4 v = *(const float4*)(src + i);
    __half2* H = (__half2*)(hi + i);
    H[0] = __half2(__float2half_rn(v.x), __float2half_rn(v.y));
    H[1] = __half2(__float2half_rn(v.z), __float2half_rn(v.w));
}

// pack Wq/Wk/Wv rows -> [1152][1024] fp16 hi
__global__ void convert_w(const float* __restrict__ Wq, const float* __restrict__ Wk,
                          const float* __restrict__ Wv) {
    int row = blockIdx.x;
    const float* src;
    if (row < 1024)      src = Wq + (size_t)row * WIDTH;
    else if (row < 1088) src = Wk + (size_t)(row - 1024) * WIDTH;
    else                 src = Wv + (size_t)(row - 1088) * WIDTH;
    int c = threadIdx.x * 4;
    float4 v = *(const float4*)(src + c);
    __half2* H = (__half2*)(g_Wh + (size_t)row * WIDTH + c);
    H[0] = __half2(__float2half_rn(v.x), __float2half_rn(v.y));
    H[1] = __half2(__float2half_rn(v.z), __float2half_rn(v.w));
}

// ---------------------------------------------------------------------------
// mma.sync GEMM: C = A @ B^T (+bias).  A = Ah + Al (fp16 x2), B = Bh (fp16).
// 2 products: AhBh + AlBh.  128x128x32 tile, 8 warps, 2-stage cp.async.
// ---------------------------------------------------------------------------
#define BK 32
#define ROWB 80
#define ARR_B (128 * ROWB)
#define STAGE_B (3 * ARR_B)           // Ah | Al | Bh
#define GEMM_SMEM (2 * STAGE_B)       // 61440 B

__global__ __launch_bounds__(256, 2)
void mmagemm(const __half* __restrict__ Ah, const __half* __restrict__ Al,
             const __half* __restrict__ Bh,
             float* __restrict__ C,
             __half* __restrict__ Ch, __half* __restrict__ Cl,
             int M, int N, int K, const float* __restrict__ bias) {
    extern __shared__ char smem[];
    uint32_t sb = smem_u32(smem);
    const int tid  = threadIdx.x;
    const int lane = tid & 31;
    const int wid  = tid >> 5;
    const int wm   = wid >> 2;
    const int wn   = wid & 3;
    const int m0 = blockIdx.y * 128;
    const int n0 = blockIdx.x * 128;
    const int NK = K / BK;
    const size_t RS = (size_t)K * 2;

    const int crow = tid >> 1;
    const int ccol = (tid & 1) * 2;
    const uint32_t s_off0 = crow * ROWB + ccol * 16;
    const char* gA0 = (const char*)Ah + (size_t)(m0 + crow) * RS + ccol * 16;
    const char* gA1 = (const char*)Al + (size_t)(m0 + crow) * RS + ccol * 16;
    const char* gB0 = (const char*)Bh + (size_t)(n0 + crow) * RS + ccol * 16;

    auto load_stage = [&](int s, int it) {
        uint32_t st = sb + s * STAGE_B;
        size_t kb = (size_t)it * (BK * 2);
        CP_ASYNC16(st + 0 * ARR_B + s_off0,      gA0 + kb);
        CP_ASYNC16(st + 0 * ARR_B + s_off0 + 16, gA0 + kb + 16);
        CP_ASYNC16(st + 1 * ARR_B + s_off0,      gA1 + kb);
        CP_ASYNC16(st + 1 * ARR_B + s_off0 + 16, gA1 + kb + 16);
        CP_ASYNC16(st + 2 * ARR_B + s_off0,      gB0 + kb);
        CP_ASYNC16(st + 2 * ARR_B + s_off0 + 16, gB0 + kb + 16);
    };

    float acc[4][4][4];
#pragma unroll
    for (int i = 0; i < 4; i++)
#pragma unroll
        for (int j = 0; j < 4; j++)
#pragma unroll
            for (int q = 0; q < 4; q++) acc[i][j][q] = 0.f;

    const int asub = lane >> 3;
    const int a_row_in = (lane & 7) + 8 * (asub & 1);
    const int a_chunk  = asub >> 1;
    const int b_row_in = (lane & 7) + 8 * (asub >> 1);
    const int b_chunk  = asub & 1;

    load_stage(0, 0); CP_COMMIT();

    for (int it = 0; it < NK; ++it) {
        if (it + 1 < NK) { load_stage((it + 1) & 1, it + 1); CP_COMMIT(); CP_WAIT1(); }
        else             { CP_WAIT0(); }
        __syncthreads();

        uint32_t st  = sb + (it & 1) * STAGE_B;
        uint32_t pAh = st;
        uint32_t pAl = st + ARR_B;
        uint32_t pBh = st + 2 * ARR_B;

#pragma unroll
        for (int kk = 0; kk < 2; kk++) {
            uint32_t ah[4][4], al[4][4], bh[2][4];
#pragma unroll
            for (int mt = 0; mt < 4; mt++) {
                uint32_t off = (uint32_t)((wm * 64 + mt * 16 + a_row_in) * ROWB +
                                          (kk * 2 + a_chunk) * 16);
                LDSM_X4(ah[mt][0], ah[mt][1], ah[mt][2], ah[mt][3], pAh + off);
                LDSM_X4(al[mt][0], al[mt][1], al[mt][2], al[mt][3], pAl + off);
            }
#pragma unroll
            for (int p = 0; p < 2; p++) {
                uint32_t off = (uint32_t)((wn * 32 + p * 16 + b_row_in) * ROWB +
                                          (kk * 2 + b_chunk) * 16);
                LDSM_X4(bh[p][0], bh[p][1], bh[p][2], bh[p][3], pBh + off);
            }
#pragma unroll
            for (int mt = 0; mt < 4; mt++)
#pragma unroll
                for (int p = 0; p < 2; p++)
#pragma unroll
                    for (int hh = 0; hh < 2; hh++) {
                        int nt = p * 2 + hh;
                        mma16816(acc[mt][nt], ah[mt], bh[p][hh * 2], bh[p][hh * 2 + 1]);
                        mma16816(acc[mt][nt], al[mt], bh[p][hh * 2], bh[p][hh * 2 + 1]);
                    }
        }
        __syncthreads();
    }

    const int gid = lane >> 2;
    const int qid = lane & 3;
#pragma unroll
    for (int mt = 0; mt < 4; mt++) {
        int r0 = m0 + wm * 64 + mt * 16 + gid;
#pragma unroll
        for (int nt = 0; nt < 4; nt++) {
            int c = n0 + wn * 32 + nt * 8 + qid * 2;
            if (C) {
                float b0 = 0.f, b1 = 0.f;
                if (bias) { b0 = bias[c]; b1 = bias[c + 1]; }
                *(float2*)&C[(size_t)r0 * N + c] =
                    make_float2(acc[mt][nt][0] + b0, acc[mt][nt][1] + b1);
                *(float2*)&C[(size_t)(r0 + 8) * N + c] =
                    make_float2(acc[mt][nt][2] + b0, acc[mt][nt][3] + b1);
            } else {
                uint32_t hi, lo;
                split2h(acc[mt][nt][0], acc[mt][nt][1], hi, lo);
                *(uint32_t*)&Ch[(size_t)r0 * N + c] = hi;
                *(uint32_t*)&Cl[(size_t)r0 * N + c] = lo;
                split2h(acc[mt][nt][2], acc[mt][nt][3], hi, lo);
                *(uint32_t*)&Ch[(size_t)(r0 + 8) * N + c] = hi;
                *(uint32_t*)&Cl[(size_t)(r0 + 8) * N + c] = lo;
            }
        }
    }
}

// ---------------------------------------------------------------------------
// Tensor-core windowed MQA flash attention.
// S = QK^T in fp16 3-product (near-exact); PV in 2-product (P split, V hi).
// Stage arrays: Kh | Kl | Vh.
// ---------------------------------------------------------------------------
#define AROWB 144
#define ATN_ARR   (64 * AROWB)
#define ATN_SQH   0
#define ATN_SQL   ATN_ARR
#define ATN_STG   (2 * ATN_ARR)
#define ATN_STGSZ (3 * ATN_ARR)       // Kh | Kl | Vh
#define ATN_SMEM  (ATN_STG + 2 * ATN_STGSZ)   // 73728 B

__global__ __launch_bounds__(128, 2)
void attn_mma() {
    extern __shared__ char smc[];
    uint32_t sb = smem_u32(smc);
    const int qt = blockIdx.x, h = blockIdx.y, b = blockIdx.z;
    const int tid = threadIdx.x, lane = tid & 31, w = tid >> 5;
    const int g = lane >> 2, qd = lane & 3;
    const int r8 = lane & 7;

    {
        const char* srcH = (const char*)g_Qh + (size_t)(b * SEQ + qt * 64) * 2304 + h * 128;
        const char* srcL = (const char*)g_Ql + (size_t)(b * SEQ + qt * 64) * 2304 + h * 128;
#pragma unroll
        for (int j = 0; j < 4; j++) {
            int lin = j * 128 + tid, row = lin >> 3, ch = lin & 7;
            CP_ASYNC16(sb + ATN_SQH + row * AROWB + ch * 16,
                       srcH + (size_t)row * 2304 + ch * 16);
            CP_ASYNC16(sb + ATN_SQL + row * AROWB + ch * 16,
                       srcL + (size_t)row * 2304 + ch * 16);
        }
    }

    auto load_kv = [&](int s, int kt) {
        size_t kb = (size_t)(b * SEQ + kt * 64) * 2304;
        uint32_t st = sb + ATN_STG + s * ATN_STGSZ;
#pragma unroll
        for (int j = 0; j < 12; j++) {
            int arr = j >> 2, lin = (j & 3) * 128 + tid;
            int row = lin >> 3, ch = lin & 7;
            const char* base = (arr == 0) ? (const char*)g_Qh + 2048
                             : (arr == 1) ? (const char*)g_Ql + 2048
                                          : (const char*)g_Qh + 2176;
            CP_ASYNC16(st + arr * ATN_ARR + row * AROWB + ch * 16,
                       base + kb + (size_t)row * 2304 + ch * 16);
        }
    };

    int ktlo = qt - 4; if (ktlo < 0) ktlo = 0;
    int kthi = qt + 4; if (kthi > SEQ / 64 - 1) kthi = SEQ / 64 - 1;

    load_kv(0, ktlo); CP_COMMIT();
    if (ktlo < kthi) { load_kv(1, ktlo + 1); CP_COMMIT(); }

    uint32_t qh[4][4], ql[4][4];
    float oacc[8][4];
#pragma unroll
    for (int i = 0; i < 8; i++)
#pragma unroll
        for (int j = 0; j < 4; j++) oacc[i][j] = 0.f;
    float m0 = -1e30f, m1 = -1e30f, l0 = 0.f, l1 = 0.f;

    for (int kt = ktlo; kt <= kthi; kt++) {
        int s = (kt - ktlo) & 1;
        if (kt < kthi) CP_WAIT1(); else CP_WAIT0();
        __syncthreads();

        if (kt == ktlo) {
#pragma unroll
            for (int ks = 0; ks < 4; ks++) {
                uint32_t off = (uint32_t)((w * 16 + (lane & 15)) * AROWB +
                                          ks * 32 + (lane >> 4) * 16);
                LDSM_X4(qh[ks][0], qh[ks][1], qh[ks][2], qh[ks][3], sb + ATN_SQH + off);
                LDSM_X4(ql[ks][0], ql[ks][1], ql[ks][2], ql[ks][3], sb + ATN_SQL + off);
            }
        }

        uint32_t stg = sb + ATN_STG + s * ATN_STGSZ;
        uint32_t pKh = stg, pKl = stg + ATN_ARR;
        uint32_t pVh = stg + 2 * ATN_ARR;

        // ---- S = Q @ K^T (3-product fp16: near-exact) ----
        float sacc[8][4];
#pragma unroll
        for (int i = 0; i < 8; i++)
#pragma unroll
            for (int j = 0; j < 4; j++) sacc[i][j] = 0.f;

#pragma unroll
        for (int ks = 0; ks < 4; ks++)
#pragma unroll
            for (int sg = 0; sg < 4; sg++) {
                uint32_t off = (uint32_t)((sg * 16 + ((lane >> 4) & 1) * 8 + r8) * AROWB +
                                          ks * 32 + ((lane >> 3) & 1) * 16);
                uint32_t kh0, kh1, kh2, kh3, kl0, kl1, kl2, kl3;
                LDSM_X4(kh0, kh1, kh2, kh3, pKh + off);
                LDSM_X4(kl0, kl1, kl2, kl3, pKl + off);
                mma16816(sacc[sg * 2],     qh[ks], kh0, kh1);
                mma16816(sacc[sg * 2],     qh[ks], kl0, kl1);
                mma16816(sacc[sg * 2],     ql[ks], kh0, kh1);
                mma16816(sacc[sg * 2 + 1], qh[ks], kh2, kh3);
                mma16816(sacc[sg * 2 + 1], qh[ks], kl2, kl3);
                mma16816(sacc[sg * 2 + 1], ql[ks], kh2, kh3);
            }

        int rel = kt - qt;
#pragma unroll
        for (int nt = 0; nt < 8; nt++)
#pragma unroll
            for (int e = 0; e < 4; e++) sacc[nt][e] *= 0.125f;
        if (rel == 4 || rel == -4) {
#pragma unroll
            for (int nt = 0; nt < 8; nt++)
#pragma unroll
                for (int e = 0; e < 4; e++) {
                    int ri = w * 16 + g + ((e >= 2) ? 8 : 0);
                    int cj = nt * 8 + 2 * qd + (e & 1);
                    bool ok = (rel == 4) ? (cj <= ri) : (cj >= ri);
                    if (!ok) sacc[nt][e] = -1e30f;
                }
        }

        float rm0 = -1e30f, rm1 = -1e30f;
#pragma unroll
        for (int nt = 0; nt < 8; nt++) {
            rm0 = fmaxf(rm0, fmaxf(sacc[nt][0], sacc[nt][1]));
            rm1 = fmaxf(rm1, fmaxf(sacc[nt][2], sacc[nt][3]));
        }
        rm0 = fmaxf(rm0, __shfl_xor_sync(0xffffffffu, rm0, 1));
        rm0 = fmaxf(rm0, __shfl_xor_sync(0xffffffffu, rm0, 2));
        rm1 = fmaxf(rm1, __shfl_xor_sync(0xffffffffu, rm1, 1));
        rm1 = fmaxf(rm1, __shfl_xor_sync(0xffffffffu, rm1, 2));
        float nm0 = fmaxf(m0, rm0), nm1 = fmaxf(m1, rm1);
        float c0 = __expf(m0 - nm0), c1 = __expf(m1 - nm1);
        m0 = nm0; m1 = nm1;

        float sum0 = 0.f, sum1 = 0.f;
#pragma unroll
        for (int nt = 0; nt < 8; nt++) {
            sacc[nt][0] = __expf(sacc[nt][0] - nm0);
            sacc[nt][1] = __expf(sacc[nt][1] - nm0);
            sacc[nt][2] = __expf(sacc[nt][2] - nm1);
            sacc[nt][3] = __expf(sacc[nt][3] - nm1);
            sum0 += sacc[nt][0] + sacc[nt][1];
            sum1 += sacc[nt][2] + sacc[nt][3];
        }
        sum0 += __shfl_xor_sync(0xffffffffu, sum0, 1);
        sum0 += __shfl_xor_sync(0xffffffffu, sum0, 2);
        sum1 += __shfl_xor_sync(0xffffffffu, sum1, 1);
        sum1 += __shfl_xor_sync(0xffffffffu, sum1, 2);
        l0 = l0 * c0 + sum0; l1 = l1 * c1 + sum1;
#pragma unroll
        for (int nt = 0; nt < 8; nt++) {
            oacc[nt][0] *= c0; oacc[nt][1] *= c0;
            oacc[nt][2] *= c1; oacc[nt][3] *= c1;
        }

        // ---- P frags (fp16 hi/lo) from S accumulators ----
        uint32_t ph[4][4], pl[4][4];
#pragma unroll
        for (int kg = 0; kg < 4; kg++) {
            split2h(sacc[2 * kg][0],     sacc[2 * kg][1],     ph[kg][0], pl[kg][0]);
            split2h(sacc[2 * kg][2],     sacc[2 * kg][3],     ph[kg][1], pl[kg][1]);
            split2h(sacc[2 * kg + 1][0], sacc[2 * kg + 1][1], ph[kg][2], pl[kg][2]);
            split2h(sacc[2 * kg + 1][2], sacc[2 * kg + 1][3], ph[kg][3], pl[kg][3]);
        }

        // ---- O += P @ V (2-product: (Ph+Pl) x Vh) ----
#pragma unroll
        for (int kg = 0; kg < 4; kg++)
#pragma unroll
            for (int dg = 0; dg < 4; dg++) {
                uint32_t off = (uint32_t)((kg * 16 + ((lane >> 3) & 1) * 8 + r8) * AROWB +
                                          dg * 32 + ((lane >> 4) & 1) * 16);
                uint32_t vh0, vh1, vh2, vh3;
                LDSM_X4T(vh0, vh1, vh2, vh3, pVh + off);
                mma16816(oacc[dg * 2],     ph[kg], vh0, vh1);
                mma16816(oacc[dg * 2],     pl[kg], vh0, vh1);
                mma16816(oacc[dg * 2 + 1], ph[kg], vh2, vh3);
                mma16816(oacc[dg * 2 + 1], pl[kg], vh2, vh3);
            }

        __syncthreads();
        if (kt + 2 <= kthi) { load_kv(s, kt + 2); CP_COMMIT(); }
    }

    float inv0 = 1.0f / l0, inv1 = 1.0f / l1;
    size_t row0 = (size_t)(b * SEQ + qt * 64 + w * 16 + g);
    size_t row1 = row0 + 8;
#pragma unroll
    for (int nt = 0; nt < 8; nt++) {
        int col = h * 64 + nt * 8 + 2 * qd;
        uint32_t hi, lo;
        split2h(oacc[nt][0] * inv0, oacc[nt][1] * inv0, hi, lo);
        *(uint32_t*)&g_Oh[row0 * WIDTH + col] = hi;
        *(uint32_t*)&g_Ol[row0 * WIDTH + col] = lo;
        split2h(oacc[nt][2] * inv1, oacc[nt][3] * inv1, hi, lo);
        *(uint32_t*)&g_Oh[row1 * WIDTH + col] = hi;
        *(uint32_t*)&g_Ol[row1 * WIDTH + col] = lo;
    }
}

// ---------------------------------------------------------------------------
// Launch
// ---------------------------------------------------------------------------
extern "C" void kernel_launch(void* const* d_in, const int* in_sizes, int n_in,
                              void* d_out, int out_size) {
    const float* x  = (const float*)d_in[0];
    const float* Wq = (const float*)d_in[1];
    const float* Wk = (const float*)d_in[2];
    const float* Wv = (const float*)d_in[3];
    const float* Wf = (const float*)d_in[4];
    const float* bf = (const float*)d_in[5];
    float* out = (float*)d_out;
    (void)in_sizes; (void)n_in; (void)out_size;

    __half *pAh, *pAl, *pWh, *pFh, *pQh, *pQl, *pOh, *pOl;
    cudaGetSymbolAddress((void**)&pAh, g_Ah);
    cudaGetSymbolAddress((void**)&pAl, g_Al);
    cudaGetSymbolAddress((void**)&pWh, g_Wh);
    cudaGetSymbolAddress((void**)&pFh, g_Fh);
    cudaGetSymbolAddress((void**)&pQh, g_Qh);
    cudaGetSymbolAddress((void**)&pQl, g_Ql);
    cudaGetSymbolAddress((void**)&pOh, g_Oh);
    cudaGetSymbolAddress((void**)&pOl, g_Ol);

    cudaFuncSetAttribute(mmagemm,
                         cudaFuncAttributeMaxDynamicSharedMemorySize, GEMM_SMEM);
    cudaFuncSetAttribute(attn_mma,
                         cudaFuncAttributeMaxDynamicSharedMemorySize, ATN_SMEM);

    convert_hl<<<TOK * WIDTH / 1024, 256>>>(x, pAh, pAl, TOK * WIDTH);
    convert_w<<<NQKV, 256>>>(Wq, Wk, Wv);
    convert_h<<<WIDTH * WIDTH / 1024, 256>>>(Wf, pFh, WIDTH * WIDTH);

    // QKV projection -> fp16 hi/lo qkv
    mmagemm<<<dim3(NQKV / 128, TOK / 128), 256, GEMM_SMEM>>>(
        pAh, pAl, pWh, nullptr, pQh, pQl, TOK, NQKV, WIDTH, nullptr);

    // tensor-core windowed attention -> fp16 hi/lo O
    attn_mma<<<dim3(SEQ / 64, NH, BATCH), 128, ATN_SMEM>>>();

    // output projection + bias -> fp32 out
    mmagemm<<<dim3(WIDTH / 128, TOK / 128), 256, GEMM_SMEM>>>(
        pOh, pOl, pFh, out, nullptr, nullptr, TOK, WIDTH, WIDTH, bf);
}